// round 8
// baseline (speedup 1.0000x reference)
#include <cuda_runtime.h>
#include <math.h>
#include <stdint.h>

#define Bc   4
#define Sc   1024
#define Dc   1024
#define Hc   16
#define DKc  64
#define Mc   (Bc*Sc)        // 4096
#define BHc  (Bc*Hc)        // 64
#define YSIZE (Bc*Sc*Dc)

// ---------------- device scratch ----------------
__device__ float g_Q[Mc*Dc];        // [bh][s][dk]  (tf32-rounded)
__device__ float g_K[Mc*Dc];        // [bh][s][dk]  (tf32-rounded)
__device__ float g_VT[Mc*Dc];       // [bh][dk][s]  (tf32-rounded)
__device__ float g_att[Mc*Dc];      // [m][h*dk]
__device__ float g_fc[Mc*Dc];       // fc + resid (fp32)
__device__ float g_WT[4][Dc*Dc];    // WT[n][k]     (tf32-rounded)

// ---------------- helpers ----------------
__device__ __forceinline__ uint32_t smem_u32(const void* p) {
    uint32_t a;
    asm("{ .reg .u64 t; cvta.to.shared.u64 t, %1; cvt.u32.u64 %0, t; }" : "=r"(a) : "l"(p));
    return a;
}
__device__ __forceinline__ float tf32r(float x) {
    uint32_t u;
    asm("cvt.rna.tf32.f32 %0, %1;" : "=r"(u) : "f"(x));
    return __uint_as_float(u);
}
__device__ __forceinline__ void mma_tf32(float* c, const float* a, const float* b) {
    asm volatile("mma.sync.aligned.m16n8k8.row.col.f32.tf32.tf32.f32 "
        "{%0,%1,%2,%3}, {%4,%5,%6,%7}, {%8,%9}, {%0,%1,%2,%3};"
        : "+f"(c[0]), "+f"(c[1]), "+f"(c[2]), "+f"(c[3])
        : "r"(__float_as_uint(a[0])), "r"(__float_as_uint(a[1])),
          "r"(__float_as_uint(a[2])), "r"(__float_as_uint(a[3])),
          "r"(__float_as_uint(b[0])), "r"(__float_as_uint(b[1])));
}
__device__ __forceinline__ void st4cvt(float* d, float4 v) {
    float4 o = make_float4(tf32r(v.x), tf32r(v.y), tf32r(v.z), tf32r(v.w));
    *(float4*)d = o;
}
__device__ __forceinline__ void cpa16(uint32_t dst, const float* src) {
    asm volatile("cp.async.cg.shared.global [%0], [%1], 16;" :: "r"(dst), "l"(src));
}
#define CP_COMMIT() asm volatile("cp.async.commit_group;" ::: "memory")
__device__ __forceinline__ void cp_wait(int n) {
    if (n == 0) asm volatile("cp.async.wait_group 0;" ::: "memory");
    else        asm volatile("cp.async.wait_group 1;" ::: "memory");
}

// ---------------- weight transpose (batched): W[k][n] -> WT[n][k], tf32 ----------------
__global__ void transpose_w(const float* __restrict__ W0, const float* __restrict__ W1,
                            const float* __restrict__ W2, const float* __restrict__ W3)
{
    __shared__ float t[32][33];
    const float* W = (blockIdx.z == 0) ? W0 : (blockIdx.z == 1) ? W1 : (blockIdx.z == 2) ? W2 : W3;
    float* o = g_WT[blockIdx.z];
    const int k0 = blockIdx.y * 32, n0 = blockIdx.x * 32;
    const int tx = threadIdx.x, ty = threadIdx.y;   // 32 x 8
#pragma unroll
    for (int i = 0; i < 32; i += 8)
        t[ty + i][tx] = W[(size_t)(k0 + ty + i) * Dc + n0 + tx];
    __syncthreads();
#pragma unroll
    for (int i = 0; i < 32; i += 8)
        o[(size_t)(n0 + ty + i) * Dc + k0 + tx] = tf32r(t[tx][ty + i]);
}

// ===========================================================================
// tf32 GEMM (unchanged from R7): C[128x128] = A @ WT^T.
// ===========================================================================
#define GST 36
#define GTILE (128*GST*4)
#define GBUF  (2*GTILE)
#define SM_G  (2*GBUF)
#define STG 132

__global__ __launch_bounds__(256, 2) void mma_gemm(const float* __restrict__ Ain,
                                                   int widx, int mode,
                                                   const float* __restrict__ bias,
                                                   const float* __restrict__ resid)
{
    extern __shared__ __align__(16) char smem[];
    const uint32_t sb = smem_u32(smem);
    const int tid  = threadIdx.x;
    const int lane = tid & 31;
    const int wid  = tid >> 5;
    const int wm   = wid >> 2;
    const int wn   = wid & 3;
    const int g    = lane >> 2;
    const int cc   = lane & 3;
    const int m0 = blockIdx.y * 128;
    const int n0 = blockIdx.x * 128;

    const float* A = (mode == 3) ? g_att : Ain;
    const float* B = g_WT[widx];

    const int fr = tid >> 3, fc = (tid & 7) * 4;
    const size_t gA = (size_t)(m0 + fr) * 1024 + fc;
    const size_t gB = (size_t)(n0 + fr) * 1024 + fc;
    const uint32_t sOffB = (fr * GST + fc) * 4;
    const uint32_t sOffA = fr * GST + fc;

    float acc[4][4][4];
#pragma unroll
    for (int i = 0; i < 4; i++)
#pragma unroll
        for (int j = 0; j < 4; j++)
#pragma unroll
            for (int q = 0; q < 4; q++) acc[i][j][q] = 0.0f;

    float4 pa[4];
#pragma unroll
    for (int j = 0; j < 4; j++)
        cpa16(sb + GTILE + sOffB + j * 32 * GST * 4, B + gB + (size_t)j * 32 * 1024);
    CP_COMMIT();
#pragma unroll
    for (int j = 0; j < 4; j++) pa[j] = *(const float4*)(A + gA + (size_t)j * 32 * 1024);
    {
        float* As = (float*)smem;
#pragma unroll
        for (int j = 0; j < 4; j++) st4cvt(As + sOffA + j * 32 * GST, pa[j]);
    }

    for (int kt = 0; kt < 32; kt++) {
        if (kt < 31) {
            const size_t ko = (size_t)(kt + 1) * 32;
            const uint32_t bb = sb + ((kt + 1) & 1) * GBUF;
#pragma unroll
            for (int j = 0; j < 4; j++)
                cpa16(bb + GTILE + sOffB + j * 32 * GST * 4, B + gB + ko + (size_t)j * 32 * 1024);
            CP_COMMIT();
#pragma unroll
            for (int j = 0; j < 4; j++) pa[j] = *(const float4*)(A + gA + ko + (size_t)j * 32 * 1024);
            cp_wait(1);
        } else {
            cp_wait(0);
        }
        __syncthreads();
        const float* As = (float*)(smem + (kt & 1) * GBUF);
        const float* Bs = As + GTILE / 4;
#pragma unroll
        for (int kk = 0; kk < 32; kk += 8) {
            float af[4][4], bf[4][2];
#pragma unroll
            for (int mi = 0; mi < 4; mi++) {
                const int row = wm * 64 + mi * 16 + g;
                af[mi][0] = As[row * GST + kk + cc];
                af[mi][1] = As[(row + 8) * GST + kk + cc];
                af[mi][2] = As[row * GST + kk + cc + 4];
                af[mi][3] = As[(row + 8) * GST + kk + cc + 4];
            }
#pragma unroll
            for (int ni = 0; ni < 4; ni++) {
                const int col = wn * 32 + ni * 8 + g;
                bf[ni][0] = Bs[col * GST + kk + cc];
                bf[ni][1] = Bs[col * GST + kk + cc + 4];
            }
#pragma unroll
            for (int mi = 0; mi < 4; mi++)
#pragma unroll
                for (int ni = 0; ni < 4; ni++)
                    mma_tf32(acc[mi][ni], af[mi], bf[ni]);
        }
        if (kt < 31) {
            float* As2 = (float*)(smem + ((kt + 1) & 1) * GBUF);
#pragma unroll
            for (int j = 0; j < 4; j++) st4cvt(As2 + sOffA + j * 32 * GST, pa[j]);
        }
        __syncthreads();
    }

    float* stage = (float*)smem;
#pragma unroll
    for (int mi = 0; mi < 4; mi++)
#pragma unroll
        for (int ni = 0; ni < 4; ni++) {
            const int row = wm * 64 + mi * 16 + (lane >> 2);
            const int col = wn * 32 + ni * 8 + (lane & 3) * 2;
            *(float2*)&stage[row * STG + col]       = make_float2(acc[mi][ni][0], acc[mi][ni][1]);
            *(float2*)&stage[(row + 8) * STG + col] = make_float2(acc[mi][ni][2], acc[mi][ni][3]);
        }
    __syncthreads();

    if (mode <= 1) {
        float* out = (mode == 0) ? g_Q : g_K;
#pragma unroll
        for (int i = 0; i < 16; i++) {
            const int e = tid + i * 256;
            const int r = e >> 5, c4 = (e & 31) * 4;
            float4 v = *(const float4*)&stage[r * STG + c4];
            const int m = m0 + r, b = m >> 10, s = m & 1023;
            const int n = n0 + c4, h = n >> 6, dk = n & 63;
            st4cvt(out + (((size_t)(b * 16 + h) * 1024 + s) * 64 + dk), v);
        }
    } else if (mode == 2) {
        const int r = tid & 127, half = tid >> 7;
        const int b = m0 >> 10, s0r = m0 & 1023;
#pragma unroll 8
        for (int j = 0; j < 64; j++) {
            const int c = half * 64 + j;
            const float v = stage[r * STG + c];
            const int n = n0 + c, hh = n >> 6, dk = n & 63;
            g_VT[((size_t)(b * 16 + hh) * 64 + dk) * 1024 + s0r + r] = tf32r(v);
        }
    } else {
#pragma unroll
        for (int i = 0; i < 16; i++) {
            const int e = tid + i * 256;
            const int r = e >> 5, c4 = (e & 31) * 4;
            float4 v = *(const float4*)&stage[r * STG + c4];
            const int m = m0 + r, n = n0 + c4;
            float4 bi = *(const float4*)(bias + n);
            float4 rs = *(const float4*)(resid + (size_t)m * 1024 + n);
            v.x += bi.x + rs.x; v.y += bi.y + rs.y;
            v.z += bi.z + rs.z; v.w += bi.w + rs.w;
            *(float4*)(g_fc + (size_t)m * 1024 + n) = v;
        }
    }
}

// ===========================================================================
// flash_mma: fused scores + online softmax + p write + PV.
// CTA = (bh, 128-q tile); 16 n-tiles of 64. Grid (8, 64), 256 thr, occ 2.
// smem (floats): Qs[128][68] | Ks[64][68] | Vs[64][68] | Ps[128][68] |
//                pmax[4][128] | psum[4][128] | rsc[128] | newm[128] | inv[128]
// ===========================================================================
#define FST 68
#define FO_QS 0
#define FO_KS (128*FST)              // 8704
#define FO_VS (FO_KS + 64*FST)       // 13056
#define FO_PS (FO_VS + 64*FST)       // 17408
#define FO_PMAX (FO_PS + 128*FST)    // 26112
#define FO_PSUM (FO_PMAX + 512)
#define FO_RSC  (FO_PSUM + 512)
#define FO_NEWM (FO_RSC + 128)
#define FO_INV  (FO_NEWM + 128)
#define SM_F ((FO_INV + 128) * 4)    // 110080 B

__global__ __launch_bounds__(256, 2) void flash_mma(const float* __restrict__ rel,
                                                    const int*   __restrict__ mask,
                                                    float* __restrict__ p)
{
    extern __shared__ __align__(16) float sf[];
    const uint32_t sb = smem_u32(sf);

    const int tid = threadIdx.x, lane = tid & 31, wid = tid >> 5;
    const int wm = wid >> 2, wn = wid & 3;
    const int g = lane >> 2, cc = lane & 3;
    const int q0 = blockIdx.x * 128, bh = blockIdx.y;
    const int b = bh >> 4, h = bh & 15;
    const size_t qkbase = (size_t)bh * Sc * DKc;
    const float* Vb = g_VT + (size_t)bh * 64 * 1024;

    // prologue: Qs + K(0)  (one group)
#pragma unroll
    for (int i = 0; i < 8; i++) {
        const int e = tid + i * 256, r = e >> 4, c = (e & 15) * 4;
        cpa16(sb + (FO_QS + r * FST + c) * 4, g_Q + qkbase + (size_t)(q0 + r) * 64 + c);
    }
#pragma unroll
    for (int i = 0; i < 4; i++) {
        const int e = tid + i * 256, r = e >> 4, c = (e & 15) * 4;
        cpa16(sb + (FO_KS + r * FST + c) * 4, g_K + qkbase + (size_t)r * 64 + c);
    }
    CP_COMMIT();

    float runm = -INFINITY, runs = 0.0f;
    float mhist[16];
    float acc2[8][4];
#pragma unroll
    for (int i = 0; i < 8; i++)
#pragma unroll
        for (int j = 0; j < 4; j++) acc2[i][j] = 0.0f;

    const int ro1 = wid * 16 + g;      // PV/O rows
    const int pr = tid >> 1, ph = (tid & 1) * 32;   // p-write owner mapping

    for (int t = 0; t < 16; t++) {
        const int n0t = t * 64;
        cp_wait(0);
        __syncthreads();                               // A: K(t) ready, Vs/Ps free
        // issue V(t)
#pragma unroll
        for (int i = 0; i < 4; i++) {
            const int e = tid + i * 256, r = e >> 4, c = (e & 15) * 4;
            cpa16(sb + (FO_VS + r * FST + c) * 4, Vb + (size_t)r * 1024 + n0t + c);
        }
        CP_COMMIT();

        // ---- S = Q K^T (tf32) ----
        float acc[4][2][4];
#pragma unroll
        for (int i = 0; i < 4; i++)
#pragma unroll
            for (int j = 0; j < 2; j++)
#pragma unroll
                for (int q = 0; q < 4; q++) acc[i][j][q] = 0.0f;
#pragma unroll
        for (int kk = 0; kk < 64; kk += 8) {
            float af[4][4], bf[2][2];
#pragma unroll
            for (int mi = 0; mi < 4; mi++) {
                const int row = wm * 64 + mi * 16 + g;
                af[mi][0] = sf[FO_QS + row * FST + kk + cc];
                af[mi][1] = sf[FO_QS + (row + 8) * FST + kk + cc];
                af[mi][2] = sf[FO_QS + row * FST + kk + cc + 4];
                af[mi][3] = sf[FO_QS + (row + 8) * FST + kk + cc + 4];
            }
#pragma unroll
            for (int ni = 0; ni < 2; ni++) {
                const int col = wn * 16 + ni * 8 + g;
                bf[ni][0] = sf[FO_KS + col * FST + kk + cc];
                bf[ni][1] = sf[FO_KS + col * FST + kk + cc + 4];
            }
#pragma unroll
            for (int mi = 0; mi < 4; mi++)
#pragma unroll
                for (int ni = 0; ni < 2; ni++)
                    mma_tf32(acc[mi][ni], af[mi], bf[ni]);
        }

        // ---- x = S/8 + rel, mask; per-warp row max ----
#pragma unroll
        for (int mi = 0; mi < 4; mi++) {
            const int r1 = wm * 64 + mi * 16 + g, r2 = r1 + 8;
            float mx1 = -INFINITY, mx2 = -INFINITY;
#pragma unroll
            for (int ni = 0; ni < 2; ni++) {
                const int nidx = n0t + wn * 16 + ni * 8 + cc * 2;
                const size_t i1 = ((size_t)(b * 1024) + q0 + r1) * 1024 + nidx;
                const size_t i2 = ((size_t)(b * 1024) + q0 + r2) * 1024 + nidx;
                float2 rr1 = *(const float2*)(rel + i1);
                float2 rr2 = *(const float2*)(rel + i2);
                int2   mm1 = *(const int2*)(mask + i1);
                int2   mm2 = *(const int2*)(mask + i2);
                acc[mi][ni][0] = mm1.x ? -1e9f : fmaf(acc[mi][ni][0], 0.125f, rr1.x);
                acc[mi][ni][1] = mm1.y ? -1e9f : fmaf(acc[mi][ni][1], 0.125f, rr1.y);
                acc[mi][ni][2] = mm2.x ? -1e9f : fmaf(acc[mi][ni][2], 0.125f, rr2.x);
                acc[mi][ni][3] = mm2.y ? -1e9f : fmaf(acc[mi][ni][3], 0.125f, rr2.y);
                mx1 = fmaxf(mx1, fmaxf(acc[mi][ni][0], acc[mi][ni][1]));
                mx2 = fmaxf(mx2, fmaxf(acc[mi][ni][2], acc[mi][ni][3]));
            }
            mx1 = fmaxf(mx1, __shfl_xor_sync(0xffffffffu, mx1, 1));
            mx1 = fmaxf(mx1, __shfl_xor_sync(0xffffffffu, mx1, 2));
            mx2 = fmaxf(mx2, __shfl_xor_sync(0xffffffffu, mx2, 1));
            mx2 = fmaxf(mx2, __shfl_xor_sync(0xffffffffu, mx2, 2));
            if (cc == 0) {
                sf[FO_PMAX + wn * 128 + r1] = mx1;
                sf[FO_PMAX + wn * 128 + r2] = mx2;
            }
        }
        __syncthreads();                               // B
        if (tid < 128) {
            float mt = fmaxf(fmaxf(sf[FO_PMAX + tid], sf[FO_PMAX + 128 + tid]),
                             fmaxf(sf[FO_PMAX + 256 + tid], sf[FO_PMAX + 384 + tid]));
            float nm = fmaxf(runm, mt);
            sf[FO_RSC + tid]  = __expf(runm - nm);
            sf[FO_NEWM + tid] = nm;
            runm = nm;
        }
        __syncthreads();                               // C
        // ---- exp, stage Ps, partial sums; rescale O ----
#pragma unroll
        for (int mi = 0; mi < 4; mi++) {
            const int r1 = wm * 64 + mi * 16 + g, r2 = r1 + 8;
            const float nm1 = sf[FO_NEWM + r1], nm2 = sf[FO_NEWM + r2];
            float s1 = 0.0f, s2 = 0.0f;
#pragma unroll
            for (int ni = 0; ni < 2; ni++) {
                const int col = wn * 16 + ni * 8 + cc * 2;
                float e00 = __expf(acc[mi][ni][0] - nm1);
                float e01 = __expf(acc[mi][ni][1] - nm1);
                float e10 = __expf(acc[mi][ni][2] - nm2);
                float e11 = __expf(acc[mi][ni][3] - nm2);
                *(float2*)&sf[FO_PS + r1 * FST + col] = make_float2(e00, e01);
                *(float2*)&sf[FO_PS + r2 * FST + col] = make_float2(e10, e11);
                s1 += e00 + e01; s2 += e10 + e11;
            }
            s1 += __shfl_xor_sync(0xffffffffu, s1, 1);
            s1 += __shfl_xor_sync(0xffffffffu, s1, 2);
            s2 += __shfl_xor_sync(0xffffffffu, s2, 1);
            s2 += __shfl_xor_sync(0xffffffffu, s2, 2);
            if (cc == 0) {
                sf[FO_PSUM + wn * 128 + r1] = s1;
                sf[FO_PSUM + wn * 128 + r2] = s2;
            }
        }
        {
            const float sc1 = sf[FO_RSC + ro1], sc2 = sf[FO_RSC + ro1 + 8];
#pragma unroll
            for (int ni = 0; ni < 8; ni++) {
                acc2[ni][0] *= sc1; acc2[ni][1] *= sc1;
                acc2[ni][2] *= sc2; acc2[ni][3] *= sc2;
            }
        }
        __syncthreads();                               // D
        if (tid < 128) {
            float st = sf[FO_PSUM + tid] + sf[FO_PSUM + 128 + tid]
                     + sf[FO_PSUM + 256 + tid] + sf[FO_PSUM + 384 + tid];
            runs = runs * sf[FO_RSC + tid] + st;
            mhist[t] = sf[FO_NEWM + tid];
        }
        // p write (exp, tile-max-referenced) — owner mapping reused at rescale
        {
            float* pdst = p + ((size_t)(bh * 1024) + q0 + pr) * 1024 + n0t + ph;
            const float* psrc = &sf[FO_PS + pr * FST + ph];
#pragma unroll
            for (int i = 0; i < 8; i++)
                *(float4*)(pdst + i * 4) = *(const float4*)(psrc + i * 4);
        }
        // issue K(t+1)
        if (t < 15) {
#pragma unroll
            for (int i = 0; i < 4; i++) {
                const int e = tid + i * 256, r = e >> 4, c = (e & 15) * 4;
                cpa16(sb + (FO_KS + r * FST + c) * 4,
                      g_K + qkbase + (size_t)(n0t + 64 + r) * 64 + c);
            }
            CP_COMMIT();
            cp_wait(1);       // V(t) done; K(t+1) may fly
        } else {
            cp_wait(0);
        }
        __syncthreads();                               // E: Vs ready, Ps staged
        // ---- O += P V ----
#pragma unroll
        for (int kk = 0; kk < 64; kk += 8) {
            float a[4], bfv[8][2];
            a[0] = sf[FO_PS + ro1 * FST + kk + cc];
            a[1] = sf[FO_PS + (ro1 + 8) * FST + kk + cc];
            a[2] = sf[FO_PS + ro1 * FST + kk + cc + 4];
            a[3] = sf[FO_PS + (ro1 + 8) * FST + kk + cc + 4];
#pragma unroll
            for (int ni = 0; ni < 8; ni++) {
                const int col = ni * 8 + g;
                bfv[ni][0] = sf[FO_VS + col * FST + kk + cc];
                bfv[ni][1] = sf[FO_VS + col * FST + kk + cc + 4];
            }
#pragma unroll
            for (int ni = 0; ni < 8; ni++)
                mma_tf32(acc2[ni], a, bfv[ni]);
        }
    }

    // ---- final: factors, O out, p rescale ----
    __syncthreads();
    if (tid < 128) {
        const float inv = 1.0f / runs;
        sf[FO_INV + tid] = inv;
#pragma unroll
        for (int t = 0; t < 16; t++)
            sf[FO_PS + t * 128 + tid] = __expf(mhist[t] - runm) * inv;
    }
    __syncthreads();
    // stage O (scaled) into Qs region
    {
        const float i1 = sf[FO_INV + ro1], i2 = sf[FO_INV + ro1 + 8];
#pragma unroll
        for (int ni = 0; ni < 8; ni++) {
            const int col = ni * 8 + cc * 2;
            *(float2*)&sf[FO_QS + ro1 * FST + col]       = make_float2(acc2[ni][0] * i1, acc2[ni][1] * i1);
            *(float2*)&sf[FO_QS + (ro1 + 8) * FST + col] = make_float2(acc2[ni][2] * i2, acc2[ni][3] * i2);
        }
    }
    // p rescale: each thread re-reads exactly what it wrote (no fence needed)
    {
#pragma unroll
        for (int t = 0; t < 16; t++) {
            const float f = sf[FO_PS + t * 128 + pr];
            float* pdst = p + ((size_t)(bh * 1024) + q0 + pr) * 1024 + t * 64 + ph;
#pragma unroll
            for (int i = 0; i < 8; i++) {
                float4 v = *(float4*)(pdst + i * 4);
                v.x *= f; v.y *= f; v.z *= f; v.w *= f;
                *(float4*)(pdst + i * 4) = v;
            }
        }
    }
    __syncthreads();
    // write g_att from Qs region
#pragma unroll
    for (int i = 0; i < 8; i++) {
        const int e = tid + i * 256, r = e >> 4, c = (e & 15) * 4;
        float4 v = *(const float4*)&sf[FO_QS + r * FST + c];
        *(float4*)(g_att + ((size_t)(b * 1024) + q0 + r) * 1024 + h * 64 + c) = v;
    }
}

// ---------------- LayerNorm ----------------
__global__ __launch_bounds__(256) void ln_kernel(const float* __restrict__ gg_,
                                                 const float* __restrict__ bta,
                                                 float* __restrict__ y)
{
    __shared__ float s1[8], s2[8];
    const int row = blockIdx.x, tid = threadIdx.x, lane = tid & 31, w = tid >> 5;
    const float* xr = g_fc + (size_t)row * 1024;

    float4 v = *(const float4*)(xr + tid * 4);
    float s = v.x + v.y + v.z + v.w;
    float q = v.x*v.x + v.y*v.y + v.z*v.z + v.w*v.w;
#pragma unroll
    for (int o = 16; o > 0; o >>= 1) {
        s += __shfl_xor_sync(0xffffffffu, s, o);
        q += __shfl_xor_sync(0xffffffffu, q, o);
    }
    if (lane == 0) { s1[w] = s; s2[w] = q; }
    __syncthreads();
    s = 0.0f; q = 0.0f;
#pragma unroll
    for (int i = 0; i < 8; i++) { s += s1[i]; q += s2[i]; }

    const float mu  = s * (1.0f / 1024.0f);
    const float var = q * (1.0f / 1024.0f) - mu * mu;
    const float rs  = rsqrtf(var + 1e-5f);

    float4 gv = *(const float4*)(gg_ + tid * 4);
    float4 bb = *(const float4*)(bta + tid * 4);
    float4 o;
    o.x = (v.x - mu) * rs * gv.x + bb.x;
    o.y = (v.y - mu) * rs * gv.y + bb.y;
    o.z = (v.z - mu) * rs * gv.z + bb.z;
    o.w = (v.w - mu) * rs * gv.w + bb.w;
    *(float4*)(y + (size_t)row * 1024 + tid * 4) = o;
}

// ---------------------------------------------------------------------------
extern "C" void kernel_launch(void* const* d_in, const int* in_sizes, int n_in,
                              void* d_out, int out_size)
{
    const float* query    = (const float*)d_in[0];
    const float* key      = (const float*)d_in[1];
    const float* value    = (const float*)d_in[2];
    const int*   mask     = (const int*)  d_in[3];
    const float* relation = (const float*)d_in[4];
    const float* Wq       = (const float*)d_in[5];
    const float* Wk       = (const float*)d_in[6];
    const float* Wv       = (const float*)d_in[7];
    const float* fc_w     = (const float*)d_in[8];
    const float* fc_b     = (const float*)d_in[9];
    const float* ln_g     = (const float*)d_in[10];
    const float* ln_b     = (const float*)d_in[11];

    float* y = (float*)d_out;
    float* p = y + (size_t)YSIZE;

    static bool attr_set = false;
    if (!attr_set) {
        cudaFuncSetAttribute(mma_gemm,  cudaFuncAttributeMaxDynamicSharedMemorySize, SM_G);
        cudaFuncSetAttribute(flash_mma, cudaFuncAttributeMaxDynamicSharedMemorySize, SM_F);
        attr_set = true;
    }

    transpose_w<<<dim3(32, 32, 4), dim3(32, 8)>>>(Wq, Wk, Wv, fc_w);

    dim3 gg(8, 32);
    mma_gemm<<<gg, 256, SM_G>>>(query, 0, 0, nullptr, nullptr);
    mma_gemm<<<gg, 256, SM_G>>>(key,   1, 1, nullptr, nullptr);
    mma_gemm<<<gg, 256, SM_G>>>(value, 2, 2, nullptr, nullptr);

    flash_mma<<<dim3(8, 64), 256, SM_F>>>(relation, mask, p);

    mma_gemm<<<gg, 256, SM_G>>>(nullptr, 3, 3, fc_b, query);
    ln_kernel<<<Mc, 256>>>(ln_g, ln_b, y);
}

// round 9
// speedup vs baseline: 1.2523x; 1.2523x over previous
#include <cuda_runtime.h>
#include <math.h>
#include <stdint.h>

#define Bc   4
#define Sc   1024
#define Dc   1024
#define Hc   16
#define DKc  64
#define Mc   (Bc*Sc)        // 4096
#define BHc  (Bc*Hc)        // 64
#define YSIZE (Bc*Sc*Dc)

// ---------------- device scratch ----------------
__device__ float g_Q[Mc*Dc];        // [bh][s][dk]  (tf32-rounded)
__device__ float g_K[Mc*Dc];        // [bh][s][dk]  (tf32-rounded)
__device__ float g_VT[Mc*Dc];       // [bh][dk][s]  (tf32-rounded)
__device__ float g_att[Mc*Dc];      // [m][h*dk]
__device__ float g_fc[Mc*Dc];       // fc + resid (fp32)
__device__ float g_WT[4][Dc*Dc];    // WT[n][k]     (tf32-rounded)
__device__ float g_inv[BHc*Sc];     // 1 / softmax row sum

// ---------------- helpers ----------------
__device__ __forceinline__ uint32_t smem_u32(const void* p) {
    uint32_t a;
    asm("{ .reg .u64 t; cvta.to.shared.u64 t, %1; cvt.u32.u64 %0, t; }" : "=r"(a) : "l"(p));
    return a;
}
__device__ __forceinline__ float tf32r(float x) {
    uint32_t u;
    asm("cvt.rna.tf32.f32 %0, %1;" : "=r"(u) : "f"(x));
    return __uint_as_float(u);
}
__device__ __forceinline__ void mma_tf32(float* c, const float* a, const float* b) {
    asm volatile("mma.sync.aligned.m16n8k8.row.col.f32.tf32.tf32.f32 "
        "{%0,%1,%2,%3}, {%4,%5,%6,%7}, {%8,%9}, {%0,%1,%2,%3};"
        : "+f"(c[0]), "+f"(c[1]), "+f"(c[2]), "+f"(c[3])
        : "r"(__float_as_uint(a[0])), "r"(__float_as_uint(a[1])),
          "r"(__float_as_uint(a[2])), "r"(__float_as_uint(a[3])),
          "r"(__float_as_uint(b[0])), "r"(__float_as_uint(b[1])));
}
__device__ __forceinline__ void st4cvt(float* d, float4 v) {
    float4 o = make_float4(tf32r(v.x), tf32r(v.y), tf32r(v.z), tf32r(v.w));
    *(float4*)d = o;
}
__device__ __forceinline__ void cpa16(uint32_t dst, const float* src) {
    asm volatile("cp.async.cg.shared.global [%0], [%1], 16;" :: "r"(dst), "l"(src));
}
#define CP_COMMIT() asm volatile("cp.async.commit_group;" ::: "memory")
__device__ __forceinline__ void cp_wait(int n) {
    if (n == 0) asm volatile("cp.async.wait_group 0;" ::: "memory");
    else        asm volatile("cp.async.wait_group 1;" ::: "memory");
}

// ---------------- weight transpose (batched): W[k][n] -> WT[n][k], tf32 ----------------
__global__ void transpose_w(const float* __restrict__ W0, const float* __restrict__ W1,
                            const float* __restrict__ W2, const float* __restrict__ W3)
{
    __shared__ float t[32][33];
    const float* W = (blockIdx.z == 0) ? W0 : (blockIdx.z == 1) ? W1 : (blockIdx.z == 2) ? W2 : W3;
    float* o = g_WT[blockIdx.z];
    const int k0 = blockIdx.y * 32, n0 = blockIdx.x * 32;
    const int tx = threadIdx.x, ty = threadIdx.y;   // 32 x 8
#pragma unroll
    for (int i = 0; i < 32; i += 8)
        t[ty + i][tx] = W[(size_t)(k0 + ty + i) * Dc + n0 + tx];
    __syncthreads();
#pragma unroll
    for (int i = 0; i < 32; i += 8)
        o[(size_t)(n0 + ty + i) * Dc + k0 + tx] = tf32r(t[tx][ty + i]);
}

// ===========================================================================
// tf32 GEMM: C[128x128] = A @ WT^T. A register-path, B via cp.async.
// modeParam=-1: mode=blockIdx.z in {0,1,2} (QKV merged); modeParam=3: fc.
// ===========================================================================
#define GST 36
#define GTILE (128*GST*4)
#define GBUF  (2*GTILE)
#define SM_G  (2*GBUF)
#define STG 132

__global__ __launch_bounds__(256, 2) void mma_gemm(const float* __restrict__ A0,
                                                   const float* __restrict__ A1,
                                                   const float* __restrict__ A2,
                                                   int modeParam,
                                                   const float* __restrict__ bias,
                                                   const float* __restrict__ resid)
{
    extern __shared__ __align__(16) char smem[];
    const uint32_t sb = smem_u32(smem);
    const int tid  = threadIdx.x;
    const int lane = tid & 31;
    const int wid  = tid >> 5;
    const int wm   = wid >> 2;
    const int wn   = wid & 3;
    const int g    = lane >> 2;
    const int cc   = lane & 3;
    const int m0 = blockIdx.y * 128;
    const int n0 = blockIdx.x * 128;

    const int mode = (modeParam >= 0) ? modeParam : (int)blockIdx.z;
    const float* A = (mode == 0) ? A0 : (mode == 1) ? A1 : (mode == 2) ? A2 : g_att;
    const float* B = g_WT[mode];

    const int fr = tid >> 3, fc = (tid & 7) * 4;
    const size_t gA = (size_t)(m0 + fr) * 1024 + fc;
    const size_t gB = (size_t)(n0 + fr) * 1024 + fc;
    const uint32_t sOffB = (fr * GST + fc) * 4;
    const uint32_t sOffA = fr * GST + fc;

    float acc[4][4][4];
#pragma unroll
    for (int i = 0; i < 4; i++)
#pragma unroll
        for (int j = 0; j < 4; j++)
#pragma unroll
            for (int q = 0; q < 4; q++) acc[i][j][q] = 0.0f;

    float4 pa[4];
#pragma unroll
    for (int j = 0; j < 4; j++)
        cpa16(sb + GTILE + sOffB + j * 32 * GST * 4, B + gB + (size_t)j * 32 * 1024);
    CP_COMMIT();
#pragma unroll
    for (int j = 0; j < 4; j++) pa[j] = *(const float4*)(A + gA + (size_t)j * 32 * 1024);
    {
        float* As = (float*)smem;
#pragma unroll
        for (int j = 0; j < 4; j++) st4cvt(As + sOffA + j * 32 * GST, pa[j]);
    }

    for (int kt = 0; kt < 32; kt++) {
        if (kt < 31) {
            const size_t ko = (size_t)(kt + 1) * 32;
            const uint32_t bb = sb + ((kt + 1) & 1) * GBUF;
#pragma unroll
            for (int j = 0; j < 4; j++)
                cpa16(bb + GTILE + sOffB + j * 32 * GST * 4, B + gB + ko + (size_t)j * 32 * 1024);
            CP_COMMIT();
#pragma unroll
            for (int j = 0; j < 4; j++) pa[j] = *(const float4*)(A + gA + ko + (size_t)j * 32 * 1024);
            cp_wait(1);
        } else {
            cp_wait(0);
        }
        __syncthreads();
        const float* As = (float*)(smem + (kt & 1) * GBUF);
        const float* Bs = As + GTILE / 4;
#pragma unroll
        for (int kk = 0; kk < 32; kk += 8) {
            float af[4][4], bf[4][2];
#pragma unroll
            for (int mi = 0; mi < 4; mi++) {
                const int row = wm * 64 + mi * 16 + g;
                af[mi][0] = As[row * GST + kk + cc];
                af[mi][1] = As[(row + 8) * GST + kk + cc];
                af[mi][2] = As[row * GST + kk + cc + 4];
                af[mi][3] = As[(row + 8) * GST + kk + cc + 4];
            }
#pragma unroll
            for (int ni = 0; ni < 4; ni++) {
                const int col = wn * 32 + ni * 8 + g;
                bf[ni][0] = Bs[col * GST + kk + cc];
                bf[ni][1] = Bs[col * GST + kk + cc + 4];
            }
#pragma unroll
            for (int mi = 0; mi < 4; mi++)
#pragma unroll
                for (int ni = 0; ni < 4; ni++)
                    mma_tf32(acc[mi][ni], af[mi], bf[ni]);
        }
        if (kt < 31) {
            float* As2 = (float*)(smem + ((kt + 1) & 1) * GBUF);
#pragma unroll
            for (int j = 0; j < 4; j++) st4cvt(As2 + sOffA + j * 32 * GST, pa[j]);
        }
        __syncthreads();
    }

    float* stage = (float*)smem;
#pragma unroll
    for (int mi = 0; mi < 4; mi++)
#pragma unroll
        for (int ni = 0; ni < 4; ni++) {
            const int row = wm * 64 + mi * 16 + (lane >> 2);
            const int col = wn * 32 + ni * 8 + (lane & 3) * 2;
            *(float2*)&stage[row * STG + col]       = make_float2(acc[mi][ni][0], acc[mi][ni][1]);
            *(float2*)&stage[(row + 8) * STG + col] = make_float2(acc[mi][ni][2], acc[mi][ni][3]);
        }
    __syncthreads();

    if (mode <= 1) {
        float* out = (mode == 0) ? g_Q : g_K;
#pragma unroll
        for (int i = 0; i < 16; i++) {
            const int e = tid + i * 256;
            const int r = e >> 5, c4 = (e & 31) * 4;
            float4 v = *(const float4*)&stage[r * STG + c4];
            const int m = m0 + r, b = m >> 10, s = m & 1023;
            const int n = n0 + c4, h = n >> 6, dk = n & 63;
            st4cvt(out + (((size_t)(b * 16 + h) * 1024 + s) * 64 + dk), v);
        }
    } else if (mode == 2) {
        const int r = tid & 127, half = tid >> 7;
        const int b = m0 >> 10, s0r = m0 & 1023;
#pragma unroll 8
        for (int j = 0; j < 64; j++) {
            const int c = half * 64 + j;
            const float v = stage[r * STG + c];
            const int n = n0 + c, hh = n >> 6, dk = n & 63;
            g_VT[((size_t)(b * 16 + hh) * 64 + dk) * 1024 + s0r + r] = tf32r(v);
        }
    } else {
#pragma unroll
        for (int i = 0; i < 16; i++) {
            const int e = tid + i * 256;
            const int r = e >> 5, c4 = (e & 31) * 4;
            float4 v = *(const float4*)&stage[r * STG + c4];
            const int m = m0 + r, n = n0 + c4;
            float4 bi = *(const float4*)(bias + n);
            float4 rs = *(const float4*)(resid + (size_t)m * 1024 + n);
            v.x += bi.x + rs.x; v.y += bi.y + rs.y;
            v.z += bi.z + rs.z; v.w += bi.w + rs.w;
            *(float4*)(g_fc + (size_t)m * 1024 + n) = v;
        }
    }
}

// ===========================================================================
// flash_mma (no-max softmax: scores bounded, exp(x) safe in fp32):
// per 128q x bh CTA, 16 n-tiles: S-mma -> exp (masked->0) -> p (unnormalized)
// + row-sum accumulation + PV-mma. Writes g_inv; pscale finalizes p.
// ===========================================================================
#define FST 68
#define FO_QS 0
#define FO_KS (128*FST)              // 8704
#define FO_VS (FO_KS + 64*FST)       // 13056
#define FO_PS (FO_VS + 64*FST)       // 17408
#define FO_PSUM (FO_PS + 128*FST)    // 26112 (4 x 128)
#define FO_RSUM (FO_PSUM + 512)      // 26624 (128)
#define SM_F ((FO_RSUM + 128) * 4)   // 107008 B -> occ 2

__global__ __launch_bounds__(256, 2) void flash_mma(const float* __restrict__ rel,
                                                    const int*   __restrict__ mask,
                                                    float* __restrict__ p)
{
    extern __shared__ __align__(16) float sf[];
    const uint32_t sb = smem_u32(sf);

    const int tid = threadIdx.x, lane = tid & 31, wid = tid >> 5;
    const int wm = wid >> 2, wn = wid & 3;
    const int g = lane >> 2, cc = lane & 3;
    const int q0 = blockIdx.x * 128, bh = blockIdx.y;
    const int b = bh >> 4, h = bh & 15;
    const size_t qkbase = (size_t)bh * Sc * DKc;
    const float* Vb = g_VT + (size_t)bh * 64 * 1024;

    if (tid < 128) sf[FO_RSUM + tid] = 0.0f;

    // prologue: Qs + K(0)
#pragma unroll
    for (int i = 0; i < 8; i++) {
        const int e = tid + i * 256, r = e >> 4, c = (e & 15) * 4;
        cpa16(sb + (FO_QS + r * FST + c) * 4, g_Q + qkbase + (size_t)(q0 + r) * 64 + c);
    }
#pragma unroll
    for (int i = 0; i < 4; i++) {
        const int e = tid + i * 256, r = e >> 4, c = (e & 15) * 4;
        cpa16(sb + (FO_KS + r * FST + c) * 4, g_K + qkbase + (size_t)r * 64 + c);
    }
    CP_COMMIT();

    float acc2[8][4];
#pragma unroll
    for (int i = 0; i < 8; i++)
#pragma unroll
        for (int j = 0; j < 4; j++) acc2[i][j] = 0.0f;

    const int ro1 = wid * 16 + g;                   // PV/O rows
    const int pr = tid >> 1, ph = (tid & 1) * 32;   // p-write owner mapping

    for (int t = 0; t < 16; t++) {
        const int n0t = t * 64;
        cp_wait(0);
        __syncthreads();                            // A: K(t) ready, Vs free (PV(t-1) done)
        // issue V(t)
#pragma unroll
        for (int i = 0; i < 4; i++) {
            const int e = tid + i * 256, r = e >> 4, c = (e & 15) * 4;
            cpa16(sb + (FO_VS + r * FST + c) * 4, Vb + (size_t)r * 1024 + n0t + c);
        }
        CP_COMMIT();

        // ---- S = Q K^T (tf32) ----
        float acc[4][2][4];
#pragma unroll
        for (int i = 0; i < 4; i++)
#pragma unroll
            for (int j = 0; j < 2; j++)
#pragma unroll
                for (int q = 0; q < 4; q++) acc[i][j][q] = 0.0f;
#pragma unroll
        for (int kk = 0; kk < 64; kk += 8) {
            float af[4][4], bf[2][2];
#pragma unroll
            for (int mi = 0; mi < 4; mi++) {
                const int row = wm * 64 + mi * 16 + g;
                af[mi][0] = sf[FO_QS + row * FST + kk + cc];
                af[mi][1] = sf[FO_QS + (row + 8) * FST + kk + cc];
                af[mi][2] = sf[FO_QS + row * FST + kk + cc + 4];
                af[mi][3] = sf[FO_QS + (row + 8) * FST + kk + cc + 4];
            }
#pragma unroll
            for (int ni = 0; ni < 2; ni++) {
                const int col = wn * 16 + ni * 8 + g;
                bf[ni][0] = sf[FO_KS + col * FST + kk + cc];
                bf[ni][1] = sf[FO_KS + col * FST + kk + cc + 4];
            }
#pragma unroll
            for (int mi = 0; mi < 4; mi++)
#pragma unroll
                for (int ni = 0; ni < 2; ni++)
                    mma_tf32(acc[mi][ni], af[mi], bf[ni]);
        }

        // ---- exp(S/8 + rel), masked -> 0; stage Ps; per-row partial sums ----
#pragma unroll
        for (int mi = 0; mi < 4; mi++) {
            const int r1 = wm * 64 + mi * 16 + g, r2 = r1 + 8;
            float s1 = 0.0f, s2 = 0.0f;
#pragma unroll
            for (int ni = 0; ni < 2; ni++) {
                const int col = wn * 16 + ni * 8 + cc * 2;
                const int nidx = n0t + col;
                const size_t i1 = ((size_t)(b * 1024) + q0 + r1) * 1024 + nidx;
                const size_t i2 = ((size_t)(b * 1024) + q0 + r2) * 1024 + nidx;
                float2 rr1 = *(const float2*)(rel + i1);
                float2 rr2 = *(const float2*)(rel + i2);
                int2   mm1 = *(const int2*)(mask + i1);
                int2   mm2 = *(const int2*)(mask + i2);
                float e00 = mm1.x ? 0.0f : __expf(fmaf(acc[mi][ni][0], 0.125f, rr1.x));
                float e01 = mm1.y ? 0.0f : __expf(fmaf(acc[mi][ni][1], 0.125f, rr1.y));
                float e10 = mm2.x ? 0.0f : __expf(fmaf(acc[mi][ni][2], 0.125f, rr2.x));
                float e11 = mm2.y ? 0.0f : __expf(fmaf(acc[mi][ni][3], 0.125f, rr2.y));
                *(float2*)&sf[FO_PS + r1 * FST + col] = make_float2(e00, e01);
                *(float2*)&sf[FO_PS + r2 * FST + col] = make_float2(e10, e11);
                s1 += e00 + e01; s2 += e10 + e11;
            }
            s1 += __shfl_xor_sync(0xffffffffu, s1, 1);
            s1 += __shfl_xor_sync(0xffffffffu, s1, 2);
            s2 += __shfl_xor_sync(0xffffffffu, s2, 1);
            s2 += __shfl_xor_sync(0xffffffffu, s2, 2);
            if (cc == 0) {
                sf[FO_PSUM + wn * 128 + r1] = s1;
                sf[FO_PSUM + wn * 128 + r2] = s2;
            }
        }
        __syncthreads();                            // B: Ps + psum complete, S reads done
        if (tid < 128)
            sf[FO_RSUM + tid] += sf[FO_PSUM + tid] + sf[FO_PSUM + 128 + tid]
                               + sf[FO_PSUM + 256 + tid] + sf[FO_PSUM + 384 + tid];
        // p write (unnormalized exp)
        {
            float* pdst = p + ((size_t)(bh * 1024) + q0 + pr) * 1024 + n0t + ph;
            const float* psrc = &sf[FO_PS + pr * FST + ph];
#pragma unroll
            for (int i = 0; i < 8; i++)
                *(float4*)(pdst + i * 4) = *(const float4*)(psrc + i * 4);
        }
        // issue K(t+1) (safe: all warps past S-mma reads at barrier B)
        if (t < 15) {
#pragma unroll
            for (int i = 0; i < 4; i++) {
                const int e = tid + i * 256, r = e >> 4, c = (e & 15) * 4;
                cpa16(sb + (FO_KS + r * FST + c) * 4,
                      g_K + qkbase + (size_t)(n0t + 64 + r) * 64 + c);
            }
            CP_COMMIT();
            cp_wait(1);      // V(t) arrived; K(t+1) in flight
        } else {
            cp_wait(0);
        }
        __syncthreads();                            // E: Vs ready, Ps staged
        // ---- O += P V ----
#pragma unroll
        for (int kk = 0; kk < 64; kk += 8) {
            float a[4], bfv[8][2];
            a[0] = sf[FO_PS + ro1 * FST + kk + cc];
            a[1] = sf[FO_PS + (ro1 + 8) * FST + kk + cc];
            a[2] = sf[FO_PS + ro1 * FST + kk + cc + 4];
            a[3] = sf[FO_PS + (ro1 + 8) * FST + kk + cc + 4];
#pragma unroll
            for (int ni = 0; ni < 8; ni++) {
                const int col = ni * 8 + g;
                bfv[ni][0] = sf[FO_VS + col * FST + kk + cc];
                bfv[ni][1] = sf[FO_VS + col * FST + kk + cc + 4];
            }
#pragma unroll
            for (int ni = 0; ni < 8; ni++)
                mma_tf32(acc2[ni], a, bfv[ni]);
        }
    }

    // ---- finalize: inv row sums, O out ----
    __syncthreads();
    if (tid < 128) {
        const float iv = 1.0f / sf[FO_RSUM + tid];
        sf[FO_RSUM + tid] = iv;
        g_inv[(size_t)bh * 1024 + q0 + tid] = iv;
    }
    __syncthreads();
    {
        const float i1 = sf[FO_RSUM + ro1], i2 = sf[FO_RSUM + ro1 + 8];
#pragma unroll
        for (int ni = 0; ni < 8; ni++) {
            const int col = ni * 8 + cc * 2;
            *(float2*)&sf[FO_QS + ro1 * FST + col]       = make_float2(acc2[ni][0] * i1, acc2[ni][1] * i1);
            *(float2*)&sf[FO_QS + (ro1 + 8) * FST + col] = make_float2(acc2[ni][2] * i2, acc2[ni][3] * i2);
        }
    }
    __syncthreads();
#pragma unroll
    for (int i = 0; i < 8; i++) {
        const int e = tid + i * 256, r = e >> 4, c = (e & 15) * 4;
        float4 v = *(const float4*)&sf[FO_QS + r * FST + c];
        *(float4*)(g_att + ((size_t)(b * 1024) + q0 + r) * 1024 + h * 64 + c) = v;
    }
}

// ---------------- pscale: p *= 1/rowsum (one row per CTA) ----------------
__global__ __launch_bounds__(256) void pscale(float* __restrict__ p)
{
    const int row = blockIdx.x;                // 0..65535 = bh*1024 + q
    const float inv = g_inv[row];
    float4* pr = (float4*)(p + (size_t)row * 1024) + threadIdx.x;
    float4 v = *pr;
    v.x *= inv; v.y *= inv; v.z *= inv; v.w *= inv;
    *pr = v;
}

// ---------------- LayerNorm ----------------
__global__ __launch_bounds__(256) void ln_kernel(const float* __restrict__ gg_,
                                                 const float* __restrict__ bta,
                                                 float* __restrict__ y)
{
    __shared__ float s1[8], s2[8];
    const int row = blockIdx.x, tid = threadIdx.x, lane = tid & 31, w = tid >> 5;
    const float* xr = g_fc + (size_t)row * 1024;

    float4 v = *(const float4*)(xr + tid * 4);
    float s = v.x + v.y + v.z + v.w;
    float q = v.x*v.x + v.y*v.y + v.z*v.z + v.w*v.w;
#pragma unroll
    for (int o = 16; o > 0; o >>= 1) {
        s += __shfl_xor_sync(0xffffffffu, s, o);
        q += __shfl_xor_sync(0xffffffffu, q, o);
    }
    if (lane == 0) { s1[w] = s; s2[w] = q; }
    __syncthreads();
    s = 0.0f; q = 0.0f;
#pragma unroll
    for (int i = 0; i < 8; i++) { s += s1[i]; q += s2[i]; }

    const float mu  = s * (1.0f / 1024.0f);
    const float var = q * (1.0f / 1024.0f) - mu * mu;
    const float rs  = rsqrtf(var + 1e-5f);

    float4 gv = *(const float4*)(gg_ + tid * 4);
    float4 bb = *(const float4*)(bta + tid * 4);
    float4 o;
    o.x = (v.x - mu) * rs * gv.x + bb.x;
    o.y = (v.y - mu) * rs * gv.y + bb.y;
    o.z = (v.z - mu) * rs * gv.z + bb.z;
    o.w = (v.w - mu) * rs * gv.w + bb.w;
    *(float4*)(y + (size_t)row * 1024 + tid * 4) = o;
}

// ---------------------------------------------------------------------------
extern "C" void kernel_launch(void* const* d_in, const int* in_sizes, int n_in,
                              void* d_out, int out_size)
{
    const float* query    = (const float*)d_in[0];
    const float* key      = (const float*)d_in[1];
    const float* value    = (const float*)d_in[2];
    const int*   mask     = (const int*)  d_in[3];
    const float* relation = (const float*)d_in[4];
    const float* Wq       = (const float*)d_in[5];
    const float* Wk       = (const float*)d_in[6];
    const float* Wv       = (const float*)d_in[7];
    const float* fc_w     = (const float*)d_in[8];
    const float* fc_b     = (const float*)d_in[9];
    const float* ln_g     = (const float*)d_in[10];
    const float* ln_b     = (const float*)d_in[11];

    float* y = (float*)d_out;
    float* p = y + (size_t)YSIZE;

    static bool attr_set = false;
    if (!attr_set) {
        cudaFuncSetAttribute(mma_gemm,  cudaFuncAttributeMaxDynamicSharedMemorySize, SM_G);
        cudaFuncSetAttribute(flash_mma, cudaFuncAttributeMaxDynamicSharedMemorySize, SM_F);
        attr_set = true;
    }

    transpose_w<<<dim3(32, 32, 4), dim3(32, 8)>>>(Wq, Wk, Wv, fc_w);

    // QKV projections: one merged launch (z selects input/output)
    mma_gemm<<<dim3(8, 32, 3), 256, SM_G>>>(query, key, value, -1, nullptr, nullptr);

    flash_mma<<<dim3(8, 64), 256, SM_F>>>(relation, mask, p);
    pscale<<<BHc * Sc, 256>>>(p);

    mma_gemm<<<dim3(8, 32, 1), 256, SM_G>>>(nullptr, nullptr, nullptr, 3, fc_b, query);
    ln_kernel<<<Mc, 256>>>(ln_g, ln_b, y);
}

// round 10
// speedup vs baseline: 1.7312x; 1.3824x over previous
#include <cuda_runtime.h>
#include <cuda_fp16.h>
#include <math.h>
#include <stdint.h>

#define Bc   4
#define Sc   1024
#define Dc   1024
#define Hc   16
#define DKc  64
#define Mc   (Bc*Sc)        // 4096
#define BHc  (Bc*Hc)        // 64
#define YSIZE (Bc*Sc*Dc)

// ---------------- device scratch ----------------
__device__ float g_Q[Mc*Dc];        // [bh][s][dk]  (tf32-rounded)
__device__ float g_K[Mc*Dc];        // [bh][s][dk]  (tf32-rounded)
__device__ float g_VT[Mc*Dc];       // [bh][dk][s]  (tf32-rounded)
__device__ float g_att[Mc*Dc];      // [m][h*dk]
__device__ float g_fc[Mc*Dc];       // fc + resid (fp32)
__device__ float g_WT[4][Dc*Dc];    // WT[n][k]     (tf32-rounded)
__device__ float g_psum[BHc*8*Sc];  // [bh][nt][q] partial row sums
__device__ __half g_pexp[(size_t)BHc*Sc*Sc];  // unnormalized exp(x), fp16

// ---------------- helpers ----------------
__device__ __forceinline__ uint32_t smem_u32(const void* p) {
    uint32_t a;
    asm("{ .reg .u64 t; cvta.to.shared.u64 t, %1; cvt.u32.u64 %0, t; }" : "=r"(a) : "l"(p));
    return a;
}
__device__ __forceinline__ float tf32r(float x) {
    uint32_t u;
    asm("cvt.rna.tf32.f32 %0, %1;" : "=r"(u) : "f"(x));
    return __uint_as_float(u);
}
__device__ __forceinline__ void mma_tf32(float* c, const float* a, const float* b) {
    asm volatile("mma.sync.aligned.m16n8k8.row.col.f32.tf32.tf32.f32 "
        "{%0,%1,%2,%3}, {%4,%5,%6,%7}, {%8,%9}, {%0,%1,%2,%3};"
        : "+f"(c[0]), "+f"(c[1]), "+f"(c[2]), "+f"(c[3])
        : "r"(__float_as_uint(a[0])), "r"(__float_as_uint(a[1])),
          "r"(__float_as_uint(a[2])), "r"(__float_as_uint(a[3])),
          "r"(__float_as_uint(b[0])), "r"(__float_as_uint(b[1])));
}
__device__ __forceinline__ void st4cvt(float* d, float4 v) {
    float4 o = make_float4(tf32r(v.x), tf32r(v.y), tf32r(v.z), tf32r(v.w));
    *(float4*)d = o;
}
__device__ __forceinline__ void cpa16(uint32_t dst, const float* src) {
    asm volatile("cp.async.cg.shared.global [%0], [%1], 16;" :: "r"(dst), "l"(src));
}
#define CP_COMMIT() asm volatile("cp.async.commit_group;" ::: "memory")
__device__ __forceinline__ void cp_wait(int n) {
    if (n == 0) asm volatile("cp.async.wait_group 0;" ::: "memory");
    else        asm volatile("cp.async.wait_group 1;" ::: "memory");
}

// ---------------- weight transpose (batched): W[k][n] -> WT[n][k], tf32 ----------------
__global__ void transpose_w(const float* __restrict__ W0, const float* __restrict__ W1,
                            const float* __restrict__ W2, const float* __restrict__ W3)
{
    __shared__ float t[32][33];
    const float* W = (blockIdx.z == 0) ? W0 : (blockIdx.z == 1) ? W1 : (blockIdx.z == 2) ? W2 : W3;
    float* o = g_WT[blockIdx.z];
    const int k0 = blockIdx.y * 32, n0 = blockIdx.x * 32;
    const int tx = threadIdx.x, ty = threadIdx.y;   // 32 x 8
#pragma unroll
    for (int i = 0; i < 32; i += 8)
        t[ty + i][tx] = W[(size_t)(k0 + ty + i) * Dc + n0 + tx];
    __syncthreads();
#pragma unroll
    for (int i = 0; i < 32; i += 8)
        o[(size_t)(n0 + ty + i) * Dc + k0 + tx] = tf32r(t[tx][ty + i]);
}

// ===========================================================================
// tf32 GEMM: C[128x128] = A @ WT^T. A register-path, B via cp.async.
// modeParam=-1: mode=blockIdx.z in {0,1,2} (QKV merged); modeParam=3: fc.
// ===========================================================================
#define GST 36
#define GTILE (128*GST*4)
#define GBUF  (2*GTILE)
#define SM_G  (2*GBUF)
#define STG 132

__global__ __launch_bounds__(256, 2) void mma_gemm(const float* __restrict__ A0,
                                                   const float* __restrict__ A1,
                                                   const float* __restrict__ A2,
                                                   int modeParam,
                                                   const float* __restrict__ bias,
                                                   const float* __restrict__ resid)
{
    extern __shared__ __align__(16) char smem[];
    const uint32_t sb = smem_u32(smem);
    const int tid  = threadIdx.x;
    const int lane = tid & 31;
    const int wid  = tid >> 5;
    const int wm   = wid >> 2;
    const int wn   = wid & 3;
    const int g    = lane >> 2;
    const int cc   = lane & 3;
    const int m0 = blockIdx.y * 128;
    const int n0 = blockIdx.x * 128;

    const int mode = (modeParam >= 0) ? modeParam : (int)blockIdx.z;
    const float* A = (mode == 0) ? A0 : (mode == 1) ? A1 : (mode == 2) ? A2 : g_att;
    const float* B = g_WT[mode];

    const int fr = tid >> 3, fc = (tid & 7) * 4;
    const size_t gA = (size_t)(m0 + fr) * 1024 + fc;
    const size_t gB = (size_t)(n0 + fr) * 1024 + fc;
    const uint32_t sOffB = (fr * GST + fc) * 4;
    const uint32_t sOffA = fr * GST + fc;

    float acc[4][4][4];
#pragma unroll
    for (int i = 0; i < 4; i++)
#pragma unroll
        for (int j = 0; j < 4; j++)
#pragma unroll
            for (int q = 0; q < 4; q++) acc[i][j][q] = 0.0f;

    float4 pa[4];
#pragma unroll
    for (int j = 0; j < 4; j++)
        cpa16(sb + GTILE + sOffB + j * 32 * GST * 4, B + gB + (size_t)j * 32 * 1024);
    CP_COMMIT();
#pragma unroll
    for (int j = 0; j < 4; j++) pa[j] = *(const float4*)(A + gA + (size_t)j * 32 * 1024);
    {
        float* As = (float*)smem;
#pragma unroll
        for (int j = 0; j < 4; j++) st4cvt(As + sOffA + j * 32 * GST, pa[j]);
    }

    for (int kt = 0; kt < 32; kt++) {
        if (kt < 31) {
            const size_t ko = (size_t)(kt + 1) * 32;
            const uint32_t bb = sb + ((kt + 1) & 1) * GBUF;
#pragma unroll
            for (int j = 0; j < 4; j++)
                cpa16(bb + GTILE + sOffB + j * 32 * GST * 4, B + gB + ko + (size_t)j * 32 * 1024);
            CP_COMMIT();
#pragma unroll
            for (int j = 0; j < 4; j++) pa[j] = *(const float4*)(A + gA + ko + (size_t)j * 32 * 1024);
            cp_wait(1);
        } else {
            cp_wait(0);
        }
        __syncthreads();
        const float* As = (float*)(smem + (kt & 1) * GBUF);
        const float* Bs = As + GTILE / 4;
#pragma unroll
        for (int kk = 0; kk < 32; kk += 8) {
            float af[4][4], bf[4][2];
#pragma unroll
            for (int mi = 0; mi < 4; mi++) {
                const int row = wm * 64 + mi * 16 + g;
                af[mi][0] = As[row * GST + kk + cc];
                af[mi][1] = As[(row + 8) * GST + kk + cc];
                af[mi][2] = As[row * GST + kk + cc + 4];
                af[mi][3] = As[(row + 8) * GST + kk + cc + 4];
            }
#pragma unroll
            for (int ni = 0; ni < 4; ni++) {
                const int col = wn * 32 + ni * 8 + g;
                bf[ni][0] = Bs[col * GST + kk + cc];
                bf[ni][1] = Bs[col * GST + kk + cc + 4];
            }
#pragma unroll
            for (int mi = 0; mi < 4; mi++)
#pragma unroll
                for (int ni = 0; ni < 4; ni++)
                    mma_tf32(acc[mi][ni], af[mi], bf[ni]);
        }
        if (kt < 31) {
            float* As2 = (float*)(smem + ((kt + 1) & 1) * GBUF);
#pragma unroll
            for (int j = 0; j < 4; j++) st4cvt(As2 + sOffA + j * 32 * GST, pa[j]);
        }
        __syncthreads();
    }

    float* stage = (float*)smem;
#pragma unroll
    for (int mi = 0; mi < 4; mi++)
#pragma unroll
        for (int ni = 0; ni < 4; ni++) {
            const int row = wm * 64 + mi * 16 + (lane >> 2);
            const int col = wn * 32 + ni * 8 + (lane & 3) * 2;
            *(float2*)&stage[row * STG + col]       = make_float2(acc[mi][ni][0], acc[mi][ni][1]);
            *(float2*)&stage[(row + 8) * STG + col] = make_float2(acc[mi][ni][2], acc[mi][ni][3]);
        }
    __syncthreads();

    if (mode <= 1) {
        float* out = (mode == 0) ? g_Q : g_K;
#pragma unroll
        for (int i = 0; i < 16; i++) {
            const int e = tid + i * 256;
            const int r = e >> 5, c4 = (e & 31) * 4;
            float4 v = *(const float4*)&stage[r * STG + c4];
            const int m = m0 + r, b = m >> 10, s = m & 1023;
            const int n = n0 + c4, h = n >> 6, dk = n & 63;
            st4cvt(out + (((size_t)(b * 16 + h) * 1024 + s) * 64 + dk), v);
        }
    } else if (mode == 2) {
        const int r = tid & 127, half = tid >> 7;
        const int b = m0 >> 10, s0r = m0 & 1023;
#pragma unroll 8
        for (int j = 0; j < 64; j++) {
            const int c = half * 64 + j;
            const float v = stage[r * STG + c];
            const int n = n0 + c, hh = n >> 6, dk = n & 63;
            g_VT[((size_t)(b * 16 + hh) * 64 + dk) * 1024 + s0r + r] = tf32r(v);
        }
    } else {
#pragma unroll
        for (int i = 0; i < 16; i++) {
            const int e = tid + i * 256;
            const int r = e >> 5, c4 = (e & 31) * 4;
            float4 v = *(const float4*)&stage[r * STG + c4];
            const int m = m0 + r, n = n0 + c4;
            float4 bi = *(const float4*)(bias + n);
            float4 rs = *(const float4*)(resid + (size_t)m * 1024 + n);
            v.x += bi.x + rs.x; v.y += bi.y + rs.y;
            v.z += bi.z + rs.z; v.w += bi.w + rs.w;
            *(float4*)(g_fc + (size_t)m * 1024 + n) = v;
        }
    }
}

// ===========================================================================
// scores (tf32), no-max softmax: pexp = exp(S/8 + rel) (masked -> 0) in fp16,
// + per-(row, n-tile) partial sums. CTA 128q x 128n, K=64. Grid (8,8,64).
// ===========================================================================
#define SST 68
#define SM_S (2*128*SST*4)          // 69632

__global__ __launch_bounds__(256, 2) void scores_mma(const float* __restrict__ rel,
                                                     const int*   __restrict__ mask)
{
    extern __shared__ __align__(16) char smem[];
    const uint32_t sb = smem_u32(smem);
    float* Qs = (float*)smem;                 // [128][68]
    float* Ks = Qs + 128 * SST;

    const int tid = threadIdx.x, lane = tid & 31, wid = tid >> 5;
    const int wm = wid >> 2, wn = wid & 3;
    const int g = lane >> 2, cc = lane & 3;
    const int bh = blockIdx.z, q0 = blockIdx.y * 128, n0 = blockIdx.x * 128;
    const size_t base = (size_t)bh * Sc * DKc;

    {
        const int fr = tid >> 4, fc = (tid & 15) * 4;
#pragma unroll
        for (int j = 0; j < 8; j++) {
            const int r = fr + j * 16;
            cpa16(sb + ((r) * SST + fc) * 4,       g_Q + base + (size_t)(q0 + r) * 64 + fc);
            cpa16(sb + ((128 + r) * SST + fc) * 4, g_K + base + (size_t)(n0 + r) * 64 + fc);
        }
        CP_COMMIT();
        cp_wait(0);
    }
    __syncthreads();

    float acc[4][4][4];
#pragma unroll
    for (int i = 0; i < 4; i++)
#pragma unroll
        for (int j = 0; j < 4; j++)
#pragma unroll
            for (int q = 0; q < 4; q++) acc[i][j][q] = 0.0f;

#pragma unroll
    for (int kk = 0; kk < 64; kk += 8) {
        float af[4][4], bf[4][2];
#pragma unroll
        for (int mi = 0; mi < 4; mi++) {
            const int row = wm * 64 + mi * 16 + g;
            af[mi][0] = Qs[row * SST + kk + cc];
            af[mi][1] = Qs[(row + 8) * SST + kk + cc];
            af[mi][2] = Qs[row * SST + kk + cc + 4];
            af[mi][3] = Qs[(row + 8) * SST + kk + cc + 4];
        }
#pragma unroll
        for (int ni = 0; ni < 4; ni++) {
            const int col = wn * 32 + ni * 8 + g;
            bf[ni][0] = Ks[col * SST + kk + cc];
            bf[ni][1] = Ks[col * SST + kk + cc + 4];
        }
#pragma unroll
        for (int mi = 0; mi < 4; mi++)
#pragma unroll
            for (int ni = 0; ni < 4; ni++)
                mma_tf32(acc[mi][ni], af[mi], bf[ni]);
    }
    __syncthreads();

    float* stage = (float*)smem;
#pragma unroll
    for (int mi = 0; mi < 4; mi++)
#pragma unroll
        for (int ni = 0; ni < 4; ni++) {
            const int row = wm * 64 + mi * 16 + (lane >> 2);
            const int col = wn * 32 + ni * 8 + (lane & 3) * 2;
            *(float2*)&stage[row * STG + col]       = make_float2(acc[mi][ni][0], acc[mi][ni][1]);
            *(float2*)&stage[(row + 8) * STG + col] = make_float2(acc[mi][ni][2], acc[mi][ni][3]);
        }
    __syncthreads();

    // epilogue: warp wid handles rows i*8+wid; exp (no max), fp16 write, row sums
    const int b = bh >> 4;
#pragma unroll
    for (int i = 0; i < 16; i++) {
        const int r = i * 8 + wid;
        const int q = q0 + r;
        const int n = n0 + lane * 4;
        float4 v = *(const float4*)&stage[r * STG + lane * 4];
        const size_t ridx = ((size_t)b * Sc + q) * Sc + n;
        float4 r4 = *(const float4*)(rel + ridx);
        int4   m4 = *(const int4*)(mask + ridx);
        float4 e;
        e.x = m4.x ? 0.0f : __expf(fmaf(v.x, 0.125f, r4.x));
        e.y = m4.y ? 0.0f : __expf(fmaf(v.y, 0.125f, r4.y));
        e.z = m4.z ? 0.0f : __expf(fmaf(v.z, 0.125f, r4.z));
        e.w = m4.w ? 0.0f : __expf(fmaf(v.w, 0.125f, r4.w));
        float s = e.x + e.y + e.z + e.w;
#pragma unroll
        for (int o = 16; o > 0; o >>= 1) s += __shfl_xor_sync(0xffffffffu, s, o);
        __half2 h0 = __float22half2_rn(make_float2(e.x, e.y));
        __half2 h1 = __float22half2_rn(make_float2(e.z, e.w));
        uint2 hw = make_uint2(*(uint32_t*)&h0, *(uint32_t*)&h1);
        *(uint2*)(g_pexp + ((size_t)bh * Sc + q) * Sc + n) = hw;
        if (lane == 0)
            g_psum[((size_t)bh * 8 + blockIdx.x) * Sc + q] = s;
    }
}

// ===========================================================================
// att (tf32): reads fp16 pexp, scales by 1/rowsum (computed in prologue from
// 8 partials), writes final fp32 p, and computes att = P @ V.
// CTA 128q x 64dk, k-tiles of 32, double-buffered. Grid (8, 64).
// ===========================================================================
#define AST 36
#define AT_PB (128*AST*4)           // 18432
#define AT_VB (64*AST*4)            // 9216
#define AT_BUF (AT_PB+AT_VB)        // 27648
#define SM_A (2*AT_BUF + 512)
#define ATG 68

__global__ __launch_bounds__(256, 2) void att_mma(float* __restrict__ p)
{
    extern __shared__ __align__(16) char smem[];
    const uint32_t sb = smem_u32(smem);
    float* sinv = (float*)(smem + 2 * AT_BUF);   // [128]

    const int tid = threadIdx.x, lane = tid & 31, wid = tid >> 5;
    const int wm = wid >> 1, wn = wid & 1;
    const int g = lane >> 2, cc = lane & 3;
    const int q0 = blockIdx.x * 128, bh = blockIdx.y;
    const __half* Pe = g_pexp + ((size_t)bh * 1024 + q0) * 1024;
    float* Pout = p + ((size_t)bh * 1024 + q0) * 1024;
    const float* Vb = g_VT + (size_t)bh * 64 * 1024;

    const int fr = tid >> 3, fc = (tid & 7) * 4;
    const uint32_t pOff = fr * AST + fc;
    const uint32_t vOffB = (fr * AST + fc) * 4;

    float acc[2][4][4];
#pragma unroll
    for (int i = 0; i < 2; i++)
#pragma unroll
        for (int j = 0; j < 4; j++)
#pragma unroll
            for (int q = 0; q < 4; q++) acc[i][j][q] = 0.0f;

    // prologue: V(0) + row inv
#pragma unroll
    for (int j = 0; j < 2; j++)
        cpa16(sb + AT_PB + vOffB + j * 32 * AST * 4, Vb + (size_t)(fr + 32 * j) * 1024 + fc);
    CP_COMMIT();
    if (tid < 128) {
        float s = 0.0f;
#pragma unroll
        for (int t = 0; t < 8; t++)
            s += g_psum[((size_t)bh * 8 + t) * Sc + q0 + tid];
        sinv[tid] = 1.0f / s;
    }
    __syncthreads();

    uint2 pe[4];
#pragma unroll
    for (int j = 0; j < 4; j++)
        pe[j] = *(const uint2*)(Pe + (size_t)(fr + 32 * j) * 1024 + fc);
    {
        float* Ps = (float*)smem;
#pragma unroll
        for (int j = 0; j < 4; j++) {
            const float s = sinv[fr + 32 * j];
            __half2* hp = (__half2*)&pe[j];
            float2 a = __half22float2(hp[0]);
            float2 bq = __half22float2(hp[1]);
            float4 pf = make_float4(a.x * s, a.y * s, bq.x * s, bq.y * s);
            *(float4*)(Pout + (size_t)(fr + 32 * j) * 1024 + fc) = pf;   // final p
            st4cvt(Ps + pOff + j * 32 * AST, pf);
        }
    }

    for (int kt = 0; kt < 32; kt++) {
        const int ktn = kt + 1;
        if (kt < 31) {
            const size_t ko = (size_t)ktn * 32;
            const uint32_t bb = sb + (ktn & 1) * AT_BUF;
#pragma unroll
            for (int j = 0; j < 2; j++)
                cpa16(bb + AT_PB + vOffB + j * 32 * AST * 4, Vb + (size_t)(fr + 32 * j) * 1024 + ko + fc);
            CP_COMMIT();
#pragma unroll
            for (int j = 0; j < 4; j++)
                pe[j] = *(const uint2*)(Pe + (size_t)(fr + 32 * j) * 1024 + ko + fc);
            cp_wait(1);
        } else {
            cp_wait(0);
        }
        __syncthreads();
        const float* Ps = (float*)(smem + (kt & 1) * AT_BUF);
        const float* Vs = Ps + AT_PB / 4;
#pragma unroll
        for (int kk = 0; kk < 32; kk += 8) {
            float af[2][4], bf[4][2];
#pragma unroll
            for (int mi = 0; mi < 2; mi++) {
                const int row = wm * 32 + mi * 16 + g;
                af[mi][0] = Ps[row * AST + kk + cc];
                af[mi][1] = Ps[(row + 8) * AST + kk + cc];
                af[mi][2] = Ps[row * AST + kk + cc + 4];
                af[mi][3] = Ps[(row + 8) * AST + kk + cc + 4];
            }
#pragma unroll
            for (int ni = 0; ni < 4; ni++) {
                const int col = wn * 32 + ni * 8 + g;
                bf[ni][0] = Vs[col * AST + kk + cc];
                bf[ni][1] = Vs[col * AST + kk + cc + 4];
            }
#pragma unroll
            for (int mi = 0; mi < 2; mi++)
#pragma unroll
                for (int ni = 0; ni < 4; ni++)
                    mma_tf32(acc[mi][ni], af[mi], bf[ni]);
        }
        if (kt < 31) {
            float* Ps2 = (float*)(smem + (ktn & 1) * AT_BUF);
            const size_t ko = (size_t)ktn * 32;
#pragma unroll
            for (int j = 0; j < 4; j++) {
                const float s = sinv[fr + 32 * j];
                __half2* hp = (__half2*)&pe[j];
                float2 a = __half22float2(hp[0]);
                float2 bq = __half22float2(hp[1]);
                float4 pf = make_float4(a.x * s, a.y * s, bq.x * s, bq.y * s);
                *(float4*)(Pout + (size_t)(fr + 32 * j) * 1024 + ko + fc) = pf;
                st4cvt(Ps2 + pOff + j * 32 * AST, pf);
            }
        }
        __syncthreads();
    }

    float* stage = (float*)smem;   // [128][68]
#pragma unroll
    for (int mi = 0; mi < 2; mi++)
#pragma unroll
        for (int ni = 0; ni < 4; ni++) {
            const int row = wm * 32 + mi * 16 + (lane >> 2);
            const int col = wn * 32 + ni * 8 + (lane & 3) * 2;
            *(float2*)&stage[row * ATG + col]       = make_float2(acc[mi][ni][0], acc[mi][ni][1]);
            *(float2*)&stage[(row + 8) * ATG + col] = make_float2(acc[mi][ni][2], acc[mi][ni][3]);
        }
    __syncthreads();

    const int b = bh >> 4, h = bh & 15;
#pragma unroll
    for (int i = 0; i < 8; i++) {
        const int e = tid + i * 256;
        const int r = e >> 4, c4 = (e & 15) * 4;
        float4 v = *(const float4*)&stage[r * ATG + c4];
        st4cvt(g_att + ((size_t)(b * 1024) + q0 + r) * 1024 + h * 64 + c4, v);
    }
}

// ---------------- LayerNorm ----------------
__global__ __launch_bounds__(256) void ln_kernel(const float* __restrict__ gg_,
                                                 const float* __restrict__ bta,
                                                 float* __restrict__ y)
{
    __shared__ float s1[8], s2[8];
    const int row = blockIdx.x, tid = threadIdx.x, lane = tid & 31, w = tid >> 5;
    const float* xr = g_fc + (size_t)row * 1024;

    float4 v = *(const float4*)(xr + tid * 4);
    float s = v.x + v.y + v.z + v.w;
    float q = v.x*v.x + v.y*v.y + v.z*v.z + v.w*v.w;
#pragma unroll
    for (int o = 16; o > 0; o >>= 1) {
        s += __shfl_xor_sync(0xffffffffu, s, o);
        q += __shfl_xor_sync(0xffffffffu, q, o);
    }
    if (lane == 0) { s1[w] = s; s2[w] = q; }
    __syncthreads();
    s = 0.0f; q = 0.0f;
#pragma unroll
    for (int i = 0; i < 8; i++) { s += s1[i]; q += s2[i]; }

    const float mu  = s * (1.0f / 1024.0f);
    const float var = q * (1.0f / 1024.0f) - mu * mu;
    const float rs  = rsqrtf(var + 1e-5f);

    float4 gv = *(const float4*)(gg_ + tid * 4);
    float4 bb = *(const float4*)(bta + tid * 4);
    float4 o;
    o.x = (v.x - mu) * rs * gv.x + bb.x;
    o.y = (v.y - mu) * rs * gv.y + bb.y;
    o.z = (v.z - mu) * rs * gv.z + bb.z;
    o.w = (v.w - mu) * rs * gv.w + bb.w;
    *(float4*)(y + (size_t)row * 1024 + tid * 4) = o;
}

// ---------------------------------------------------------------------------
extern "C" void kernel_launch(void* const* d_in, const int* in_sizes, int n_in,
                              void* d_out, int out_size)
{
    const float* query    = (const float*)d_in[0];
    const float* key      = (const float*)d_in[1];
    const float* value    = (const float*)d_in[2];
    const int*   mask     = (const int*)  d_in[3];
    const float* relation = (const float*)d_in[4];
    const float* Wq       = (const float*)d_in[5];
    const float* Wk       = (const float*)d_in[6];
    const float* Wv       = (const float*)d_in[7];
    const float* fc_w     = (const float*)d_in[8];
    const float* fc_b     = (const float*)d_in[9];
    const float* ln_g     = (const float*)d_in[10];
    const float* ln_b     = (const float*)d_in[11];

    float* y = (float*)d_out;
    float* p = y + (size_t)YSIZE;

    static bool attr_set = false;
    if (!attr_set) {
        cudaFuncSetAttribute(mma_gemm,   cudaFuncAttributeMaxDynamicSharedMemorySize, SM_G);
        cudaFuncSetAttribute(scores_mma, cudaFuncAttributeMaxDynamicSharedMemorySize, SM_S);
        cudaFuncSetAttribute(att_mma,    cudaFuncAttributeMaxDynamicSharedMemorySize, SM_A);
        attr_set = true;
    }

    transpose_w<<<dim3(32, 32, 4), dim3(32, 8)>>>(Wq, Wk, Wv, fc_w);

    // QKV projections: one merged launch
    mma_gemm<<<dim3(8, 32, 3), 256, SM_G>>>(query, key, value, -1, nullptr, nullptr);

    scores_mma<<<dim3(8, 8, 64), 256, SM_S>>>(relation, mask);
    att_mma<<<dim3(8, 64), 256, SM_A>>>(p);

    mma_gemm<<<dim3(8, 32, 1), 256, SM_G>>>(nullptr, nullptr, nullptr, 3, fc_b, query);
    ln_kernel<<<Mc, 256>>>(ln_g, ln_b, y);
}

// round 12
// speedup vs baseline: 2.3562x; 1.3610x over previous
#include <cuda_runtime.h>
#include <cuda_fp16.h>
#include <math.h>
#include <stdint.h>

#define Bc   4
#define Sc   1024
#define Dc   1024
#define Hc   16
#define DKc  64
#define Mc   (Bc*Sc)        // 4096
#define BHc  (Bc*Hc)        // 64
#define YSIZE (Bc*Sc*Dc)

// ---------------- device scratch ----------------
__device__ __half g_Q[Mc*Dc];       // [bh][s][dk] fp16
__device__ __half g_K[Mc*Dc];       // [bh][s][dk] fp16
__device__ __half g_VT[Mc*Dc];      // [bh][dk][s] fp16
__device__ __half g_att[Mc*Dc];     // [m][h*dk]  fp16
__device__ float g_fc[Mc*Dc];       // fc + resid (fp32)
__device__ __half g_WT[4][Dc*Dc];   // WT[n][k] fp16
__device__ float g_psum[BHc*8*Sc];  // [bh][nt][q] partial row sums
__device__ __half g_pexp[(size_t)BHc*Sc*Sc];  // unnormalized exp(x), fp16

// ---------------- helpers ----------------
__device__ __forceinline__ uint32_t smem_u32(const void* p) {
    uint32_t a;
    asm("{ .reg .u64 t; cvta.to.shared.u64 t, %1; cvt.u32.u64 %0, t; }" : "=r"(a) : "l"(p));
    return a;
}
__device__ __forceinline__ uint32_t packh2(float x, float y) {
    __half2 h = __float22half2_rn(make_float2(x, y));
    return *(uint32_t*)&h;
}
__device__ __forceinline__ void ldsm4(uint32_t* r, uint32_t addr) {
    asm volatile("ldmatrix.sync.aligned.m8n8.x4.shared.b16 {%0,%1,%2,%3}, [%4];"
        : "=r"(r[0]), "=r"(r[1]), "=r"(r[2]), "=r"(r[3]) : "r"(addr));
}
__device__ __forceinline__ void mma_f16(float* c, const uint32_t* a, const uint32_t* b) {
    asm volatile("mma.sync.aligned.m16n8k16.row.col.f32.f16.f16.f32 "
        "{%0,%1,%2,%3}, {%4,%5,%6,%7}, {%8,%9}, {%0,%1,%2,%3};"
        : "+f"(c[0]), "+f"(c[1]), "+f"(c[2]), "+f"(c[3])
        : "r"(a[0]), "r"(a[1]), "r"(a[2]), "r"(a[3]), "r"(b[0]), "r"(b[1]));
}
__device__ __forceinline__ void cpa16(uint32_t dst, const void* src) {
    asm volatile("cp.async.cg.shared.global [%0], [%1], 16;" :: "r"(dst), "l"(src));
}
#define CP_COMMIT() asm volatile("cp.async.commit_group;" ::: "memory")
__device__ __forceinline__ void cp_wait(int n) {
    if (n == 0) asm volatile("cp.async.wait_group 0;" ::: "memory");
    else        asm volatile("cp.async.wait_group 1;" ::: "memory");
}

// ---------------- weight transpose: W[k][n] -> WT[n][k] fp16 ----------------
__global__ void transpose_w(const float* __restrict__ W0, const float* __restrict__ W1,
                            const float* __restrict__ W2, const float* __restrict__ W3)
{
    __shared__ float t[32][33];
    const float* W = (blockIdx.z == 0) ? W0 : (blockIdx.z == 1) ? W1 : (blockIdx.z == 2) ? W2 : W3;
    __half* o = g_WT[blockIdx.z];
    const int k0 = blockIdx.y * 32, n0 = blockIdx.x * 32;
    const int tx = threadIdx.x, ty = threadIdx.y;   // 32 x 8
#pragma unroll
    for (int i = 0; i < 32; i += 8)
        t[ty + i][tx] = W[(size_t)(k0 + ty + i) * Dc + n0 + tx];
    __syncthreads();
#pragma unroll
    for (int i = 0; i < 32; i += 8)
        o[(size_t)(n0 + ty + i) * Dc + k0 + tx] = __float2half(t[tx][ty + i]);
}

// ===========================================================================
// fp16 GEMM: C[128x128] = A @ WT^T (m16n8k16). B (fp16) via cp.async.
// modeParam=-1: mode = blockIdx.z in {0,1,2}, A = fp32 input (register path).
// modeParam=3: A = g_att fp16 via cp.async; epilogue +bias+resid -> g_fc.
// smem tiles 128 rows x 32 k fp16, row stride 80 B.
// ===========================================================================
#define GRS 80
#define GTILE 10240
#define GBUF  (2*GTILE)             // A+B per stage
#define SM_G  (128*132*4)           // 67584 (stage dominates)
#define STG 132

__global__ __launch_bounds__(256, 2) void mma_gemm(const float* __restrict__ A0,
                                                   const float* __restrict__ A1,
                                                   const float* __restrict__ A2,
                                                   int modeParam,
                                                   const float* __restrict__ bias,
                                                   const float* __restrict__ resid)
{
    extern __shared__ __align__(16) char smem[];
    const uint32_t sb = smem_u32(smem);
    const int tid  = threadIdx.x;
    const int lane = tid & 31;
    const int wid  = tid >> 5;
    const int wm   = wid >> 2;          // 0..1
    const int wn   = wid & 3;           // 0..3
    const int m0 = blockIdx.y * 128;
    const int n0 = blockIdx.x * 128;

    const int mode = (modeParam >= 0) ? modeParam : (int)blockIdx.z;
    const bool a16 = (mode == 3);
    const float* Af = (mode == 0) ? A0 : (mode == 1) ? A1 : A2;
    const __half* B = g_WT[mode];

    // fp32-A register path mapping (16 floats/thread/chunk)
    const int fr3 = tid >> 3, fc3 = (tid & 7) * 4;
    // fp16 cp.async fill: 128x32 tile needs 2 cpa16/thread
    const int ra0 = tid >> 2,          ca0 = (tid & 3) * 8;
    const int ra1 = (tid + 256) >> 2,  ca1 = ((tid + 256) & 3) * 8;
    const uint32_t sA0 = ra0 * GRS + ca0 * 2;
    const uint32_t sA1 = ra1 * GRS + ca1 * 2;

    // ldmatrix offsets
    const int arow = lane & 15;
    const int acol = (lane & 16) ? 8 : 0;
    const int brow = ((lane & 16) >> 1) + (lane & 7);
    const int bcol = (lane & 8);

    float acc[4][4][4];
#pragma unroll
    for (int i = 0; i < 4; i++)
#pragma unroll
        for (int j = 0; j < 4; j++)
#pragma unroll
            for (int q = 0; q < 4; q++) acc[i][j][q] = 0.0f;

    float4 pa[4];
    // prologue: chunk 0 into buf0
    cpa16(sb + GTILE + sA0, B + (size_t)(n0 + ra0) * 1024 + ca0);
    cpa16(sb + GTILE + sA1, B + (size_t)(n0 + ra1) * 1024 + ca1);
    if (a16) {
        cpa16(sb + sA0, g_att + (size_t)(m0 + ra0) * 1024 + ca0);
        cpa16(sb + sA1, g_att + (size_t)(m0 + ra1) * 1024 + ca1);
    }
    CP_COMMIT();
    if (!a16) {
#pragma unroll
        for (int j = 0; j < 4; j++)
            pa[j] = *(const float4*)(Af + (size_t)(m0 + fr3 + 32 * j) * 1024 + fc3);
        char* As = smem;
#pragma unroll
        for (int j = 0; j < 4; j++) {
            uint2 h = make_uint2(packh2(pa[j].x, pa[j].y), packh2(pa[j].z, pa[j].w));
            *(uint2*)(As + (fr3 + 32 * j) * GRS + fc3 * 2) = h;
        }
    }

    for (int kt = 0; kt < 32; kt++) {
        if (kt < 31) {
            const int ko = (kt + 1) * 32;
            const uint32_t bb = sb + ((kt + 1) & 1) * GBUF;
            cpa16(bb + GTILE + sA0, B + (size_t)(n0 + ra0) * 1024 + ko + ca0);
            cpa16(bb + GTILE + sA1, B + (size_t)(n0 + ra1) * 1024 + ko + ca1);
            if (a16) {
                cpa16(bb + sA0, g_att + (size_t)(m0 + ra0) * 1024 + ko + ca0);
                cpa16(bb + sA1, g_att + (size_t)(m0 + ra1) * 1024 + ko + ca1);
            }
            CP_COMMIT();
            if (!a16) {
#pragma unroll
                for (int j = 0; j < 4; j++)
                    pa[j] = *(const float4*)(Af + (size_t)(m0 + fr3 + 32 * j) * 1024 + ko + fc3);
            }
            cp_wait(1);
        } else {
            cp_wait(0);
        }
        __syncthreads();
        const uint32_t aB = sb + (kt & 1) * GBUF;
        const uint32_t bB = aB + GTILE;
#pragma unroll
        for (int ks = 0; ks < 2; ks++) {
            const int k0s = ks * 16;
            uint32_t af[4][4], bf[2][4];
#pragma unroll
            for (int mi = 0; mi < 4; mi++)
                ldsm4(af[mi], aB + (uint32_t)(wm*64 + mi*16 + arow) * GRS + (k0s + acol) * 2);
#pragma unroll
            for (int j = 0; j < 2; j++)
                ldsm4(bf[j], bB + (uint32_t)(wn*32 + j*16 + brow) * GRS + (k0s + bcol) * 2);
#pragma unroll
            for (int mi = 0; mi < 4; mi++)
#pragma unroll
                for (int ni = 0; ni < 4; ni++)
                    mma_f16(acc[mi][ni], af[mi], &bf[ni >> 1][(ni & 1) * 2]);
        }
        if (kt < 31 && !a16) {
            char* As2 = smem + ((kt + 1) & 1) * GBUF;
#pragma unroll
            for (int j = 0; j < 4; j++) {
                uint2 h = make_uint2(packh2(pa[j].x, pa[j].y), packh2(pa[j].z, pa[j].w));
                *(uint2*)(As2 + (fr3 + 32 * j) * GRS + fc3 * 2) = h;
            }
        }
        __syncthreads();
    }

    float* stage = (float*)smem;
#pragma unroll
    for (int mi = 0; mi < 4; mi++)
#pragma unroll
        for (int ni = 0; ni < 4; ni++) {
            const int row = wm * 64 + mi * 16 + (lane >> 2);
            const int col = wn * 32 + ni * 8 + (lane & 3) * 2;
            *(float2*)&stage[row * STG + col]       = make_float2(acc[mi][ni][0], acc[mi][ni][1]);
            *(float2*)&stage[(row + 8) * STG + col] = make_float2(acc[mi][ni][2], acc[mi][ni][3]);
        }
    __syncthreads();

    if (mode <= 1) {
        __half* out = (mode == 0) ? g_Q : g_K;
#pragma unroll
        for (int i = 0; i < 16; i++) {
            const int e = tid + i * 256;
            const int r = e >> 5, c4 = (e & 31) * 4;
            float4 v = *(const float4*)&stage[r * STG + c4];
            const int m = m0 + r, b = m >> 10, s = m & 1023;
            const int n = n0 + c4, h = n >> 6, dk = n & 63;
            uint2 hv = make_uint2(packh2(v.x, v.y), packh2(v.z, v.w));
            *(uint2*)(out + (((size_t)(b * 16 + h) * 1024 + s) * 64 + dk)) = hv;
        }
    } else if (mode == 2) {
        const int r = tid & 127, half_ = tid >> 7;
        const int b = m0 >> 10, s0r = m0 & 1023;
#pragma unroll 8
        for (int j = 0; j < 64; j++) {
            const int c = half_ * 64 + j;
            const float v = stage[r * STG + c];
            const int n = n0 + c, hh = n >> 6, dk = n & 63;
            g_VT[((size_t)(b * 16 + hh) * 64 + dk) * 1024 + s0r + r] = __float2half(v);
        }
    } else {
#pragma unroll
        for (int i = 0; i < 16; i++) {
            const int e = tid + i * 256;
            const int r = e >> 5, c4 = (e & 31) * 4;
            float4 v = *(const float4*)&stage[r * STG + c4];
            const int m = m0 + r, n = n0 + c4;
            float4 bi = *(const float4*)(bias + n);
            float4 rs = *(const float4*)(resid + (size_t)m * 1024 + n);
            v.x += bi.x + rs.x; v.y += bi.y + rs.y;
            v.z += bi.z + rs.z; v.w += bi.w + rs.w;
            *(float4*)(g_fc + (size_t)m * 1024 + n) = v;
        }
    }
}

// ===========================================================================
// scores (fp16 mma, no-max softmax): pexp = exp(S/8+rel) (mask->0) fp16 +
// per-(row, n-tile) sums. CTA 128q x 128n, K=64. Grid (8,8,64).
// Q/K tiles 128 x 64 fp16, row stride 144 B.
// ===========================================================================
#define SRS 144
#define SM_S (128*132*4)            // 67584 stage; tiles 36864 fit inside

__global__ __launch_bounds__(256, 2) void scores_mma(const float* __restrict__ rel,
                                                     const int*   __restrict__ mask)
{
    extern __shared__ __align__(16) char smem[];
    const uint32_t sb = smem_u32(smem);
    const uint32_t qB = sb, kB = sb + 128 * SRS;

    const int tid = threadIdx.x, lane = tid & 31, wid = tid >> 5;
    const int wm = wid >> 2, wn = wid & 3;
    const int bh = blockIdx.z, q0 = blockIdx.y * 128, n0 = blockIdx.x * 128;
    const size_t base = (size_t)bh * Sc * DKc;

    const int arow = lane & 15;
    const int acol = (lane & 16) ? 8 : 0;
    const int brow = ((lane & 16) >> 1) + (lane & 7);
    const int bcol = (lane & 8);

    {
#pragma unroll
        for (int i = 0; i < 4; i++) {
            const int e = tid + i * 256;
            const int r = e >> 3, c16 = (e & 7) * 8;
            cpa16(qB + (uint32_t)r * SRS + c16 * 2, g_Q + base + (size_t)(q0 + r) * 64 + c16);
            cpa16(kB + (uint32_t)r * SRS + c16 * 2, g_K + base + (size_t)(n0 + r) * 64 + c16);
        }
        CP_COMMIT();
        cp_wait(0);
    }
    __syncthreads();

    float acc[4][4][4];
#pragma unroll
    for (int i = 0; i < 4; i++)
#pragma unroll
        for (int j = 0; j < 4; j++)
#pragma unroll
            for (int q = 0; q < 4; q++) acc[i][j][q] = 0.0f;

#pragma unroll
    for (int ks = 0; ks < 4; ks++) {
        const int k0s = ks * 16;
        uint32_t af[4][4], bf[2][4];
#pragma unroll
        for (int mi = 0; mi < 4; mi++)
            ldsm4(af[mi], qB + (uint32_t)(wm*64 + mi*16 + arow) * SRS + (k0s + acol) * 2);
#pragma unroll
        for (int j = 0; j < 2; j++)
            ldsm4(bf[j], kB + (uint32_t)(wn*32 + j*16 + brow) * SRS + (k0s + bcol) * 2);
#pragma unroll
        for (int mi = 0; mi < 4; mi++)
#pragma unroll
            for (int ni = 0; ni < 4; ni++)
                mma_f16(acc[mi][ni], af[mi], &bf[ni >> 1][(ni & 1) * 2]);
    }
    __syncthreads();

    float* stage = (float*)smem;
#pragma unroll
    for (int mi = 0; mi < 4; mi++)
#pragma unroll
        for (int ni = 0; ni < 4; ni++) {
            const int row = wm * 64 + mi * 16 + (lane >> 2);
            const int col = wn * 32 + ni * 8 + (lane & 3) * 2;
            *(float2*)&stage[row * STG + col]       = make_float2(acc[mi][ni][0], acc[mi][ni][1]);
            *(float2*)&stage[(row + 8) * STG + col] = make_float2(acc[mi][ni][2], acc[mi][ni][3]);
        }
    __syncthreads();

    const int b = bh >> 4;
#pragma unroll
    for (int i = 0; i < 16; i++) {
        const int r = i * 8 + wid;
        const int q = q0 + r;
        const int n = n0 + lane * 4;
        float4 v = *(const float4*)&stage[r * STG + lane * 4];
        const size_t ridx = ((size_t)b * Sc + q) * Sc + n;
        float4 r4 = *(const float4*)(rel + ridx);
        int4   m4 = *(const int4*)(mask + ridx);
        float4 e;
        e.x = m4.x ? 0.0f : __expf(fmaf(v.x, 0.125f, r4.x));
        e.y = m4.y ? 0.0f : __expf(fmaf(v.y, 0.125f, r4.y));
        e.z = m4.z ? 0.0f : __expf(fmaf(v.z, 0.125f, r4.z));
        e.w = m4.w ? 0.0f : __expf(fmaf(v.w, 0.125f, r4.w));
        float s = e.x + e.y + e.z + e.w;
#pragma unroll
        for (int o = 16; o > 0; o >>= 1) s += __shfl_xor_sync(0xffffffffu, s, o);
        uint2 hw = make_uint2(packh2(e.x, e.y), packh2(e.z, e.w));
        *(uint2*)(g_pexp + ((size_t)bh * Sc + q) * Sc + n) = hw;
        if (lane == 0)
            g_psum[((size_t)bh * 8 + blockIdx.x) * Sc + q] = s;
    }
}

// ===========================================================================
// att (fp16 mma): P = raw pexp fp16 via cp.async; O = inv * (Pexp @ V).
// Writes final fp32 p from the smem tile (pexp * inv).
// CTA 128q x 64dk, k-tiles of 32, double-buffered. Grid (8, 64).
// ===========================================================================
#define AST 80                      // bytes/row (32 fp16 + pad)
#define AT_PB (128*AST)             // 10240
#define AT_VB (64*AST)              // 5120
#define AT_BUF (AT_PB+AT_VB)        // 15360
#define AT_SINV (34816)             // past stage region
#define SM_A (AT_SINV + 512)        // 35328
#define ATG 68

__global__ __launch_bounds__(256, 2) void att_mma(float* __restrict__ p)
{
    extern __shared__ __align__(16) char smem[];
    const uint32_t sb = smem_u32(smem);
    float* sinv = (float*)(smem + AT_SINV);   // [128]

    const int tid = threadIdx.x, lane = tid & 31, wid = tid >> 5;
    const int wm = wid >> 1, wn = wid & 1;
    const int q0 = blockIdx.x * 128, bh = blockIdx.y;
    const __half* Pe = g_pexp + ((size_t)bh * 1024 + q0) * 1024;
    float* Pout = p + ((size_t)bh * 1024 + q0) * 1024;
    const __half* Vb = g_VT + (size_t)bh * 64 * 1024;

    // P fill: 128x32 tile, 2 cpa16/thread
    const int ra0 = tid >> 2,          ca0 = (tid & 3) * 8;
    const int ra1 = (tid + 256) >> 2,  ca1 = ((tid + 256) & 3) * 8;
    const uint32_t sP0 = ra0 * AST + ca0 * 2;
    const uint32_t sP1 = ra1 * AST + ca1 * 2;
    // V fill: 64x32 tile, 1 cpa16/thread
    const int rv = tid >> 2,           cv = (tid & 3) * 8;
    const uint32_t sV = rv * AST + cv * 2;
    // final-p owner mapping (full row coverage: halves h16..h16+15)
    const int r2 = tid >> 1, h16 = (tid & 1) * 16;

    const int arow = lane & 15;
    const int acol = (lane & 16) ? 8 : 0;
    const int brow = ((lane & 16) >> 1) + (lane & 7);
    const int bcol = (lane & 8);

    float acc[2][4][4];
#pragma unroll
    for (int i = 0; i < 2; i++)
#pragma unroll
        for (int j = 0; j < 4; j++)
#pragma unroll
            for (int q = 0; q < 4; q++) acc[i][j][q] = 0.0f;

    // prologue: P(0) + V(0); compute sinv
    cpa16(sb + sP0,         Pe + (size_t)ra0 * 1024 + ca0);
    cpa16(sb + sP1,         Pe + (size_t)ra1 * 1024 + ca1);
    cpa16(sb + AT_PB + sV,  Vb + (size_t)rv * 1024 + cv);
    CP_COMMIT();
    if (tid < 128) {
        float s = 0.0f;
#pragma unroll
        for (int t = 0; t < 8; t++)
            s += g_psum[((size_t)bh * 8 + t) * Sc + q0 + tid];
        sinv[tid] = 1.0f / s;
    }

    for (int kt = 0; kt < 32; kt++) {
        if (kt < 31) {
            const int ko = (kt + 1) * 32;
            const uint32_t bb = sb + ((kt + 1) & 1) * AT_BUF;
            cpa16(bb + sP0,        Pe + (size_t)ra0 * 1024 + ko + ca0);
            cpa16(bb + sP1,        Pe + (size_t)ra1 * 1024 + ko + ca1);
            cpa16(bb + AT_PB + sV, Vb + (size_t)rv * 1024 + ko + cv);
            CP_COMMIT();
            cp_wait(1);
        } else {
            cp_wait(0);
        }
        __syncthreads();
        const uint32_t pB = sb + (kt & 1) * AT_BUF;
        const uint32_t vB = pB + AT_PB;
        const __half* Ps = (const __half*)(smem + (kt & 1) * AT_BUF);

        // final p write: pexp (smem) * inv -> fp32 global
        {
            const float s = sinv[r2];
            float* pd = Pout + (size_t)r2 * 1024 + kt * 32 + h16;
            const __half* psrc = Ps + r2 * (AST / 2) + h16;
#pragma unroll
            for (int j = 0; j < 4; j++) {
                __half2 a = *(const __half2*)(psrc + j * 4);
                __half2 bq = *(const __half2*)(psrc + j * 4 + 2);
                float2 fa = __half22float2(a), fb = __half22float2(bq);
                *(float4*)(pd + j * 4) = make_float4(fa.x * s, fa.y * s, fb.x * s, fb.y * s);
            }
        }

#pragma unroll
        for (int ks = 0; ks < 2; ks++) {
            const int k0s = ks * 16;
            uint32_t af[2][4], bf[2][4];
#pragma unroll
            for (int mi = 0; mi < 2; mi++)
                ldsm4(af[mi], pB + (uint32_t)(wm*32 + mi*16 + arow) * AST + (k0s + acol) * 2);
#pragma unroll
            for (int j = 0; j < 2; j++)
                ldsm4(bf[j], vB + (uint32_t)(wn*32 + j*16 + brow) * AST + (k0s + bcol) * 2);
#pragma unroll
            for (int mi = 0; mi < 2; mi++)
#pragma unroll
                for (int ni = 0; ni < 4; ni++)
                    mma_f16(acc[mi][ni], af[mi], &bf[ni >> 1][(ni & 1) * 2]);
        }
        __syncthreads();
    }

    // epilogue: O *= inv (sinv lives past the stage region)
    float* stage = (float*)smem;   // [128][68]
#pragma unroll
    for (int mi = 0; mi < 2; mi++) {
        const int row = wm * 32 + mi * 16 + (lane >> 2);
        const float i1 = sinv[row], i2 = sinv[row + 8];
#pragma unroll
        for (int ni = 0; ni < 4; ni++) {
            const int col = wn * 32 + ni * 8 + (lane & 3) * 2;
            *(float2*)&stage[row * ATG + col]       = make_float2(acc[mi][ni][0] * i1, acc[mi][ni][1] * i1);
            *(float2*)&stage[(row + 8) * ATG + col] = make_float2(acc[mi][ni][2] * i2, acc[mi][ni][3] * i2);
        }
    }
    __syncthreads();

    const int b = bh >> 4, h = bh & 15;
#pragma unroll
    for (int i = 0; i < 8; i++) {
        const int e = tid + i * 256;
        const int r = e >> 4, c4 = (e & 15) * 4;
        float4 v = *(const float4*)&stage[r * ATG + c4];
        uint2 hv = make_uint2(packh2(v.x, v.y), packh2(v.z, v.w));
        *(uint2*)(g_att + ((size_t)(b * 1024) + q0 + r) * 1024 + h * 64 + c4) = hv;
    }
}

// ---------------- LayerNorm ----------------
__global__ __launch_bounds__(256) void ln_kernel(const float* __restrict__ gg_,
                                                 const float* __restrict__ bta,
                                                 float* __restrict__ y)
{
    __shared__ float s1[8], s2[8];
    const int row = blockIdx.x, tid = threadIdx.x, lane = tid & 31, w = tid >> 5;
    const float* xr = g_fc + (size_t)row * 1024;

    float4 v = *(const float4*)(xr + tid * 4);
    float s = v.x + v.y + v.z + v.w;
    float q = v.x*v.x + v.y*v.y + v.z*v.z + v.w*v.w;
#pragma unroll
    for (int o = 16; o > 0; o >>= 1) {
        s += __shfl_xor_sync(0xffffffffu, s, o);
        q += __shfl_xor_sync(0xffffffffu, q, o);
    }
    if (lane == 0) { s1[w] = s; s2[w] = q; }
    __syncthreads();
    s = 0.0f; q = 0.0f;
#pragma unroll
    for (int i = 0; i < 8; i++) { s += s1[i]; q += s2[i]; }

    const float mu  = s * (1.0f / 1024.0f);
    const float var = q * (1.0f / 1024.0f) - mu * mu;
    const float rs  = rsqrtf(var + 1e-5f);

    float4 gv = *(const float4*)(gg_ + tid * 4);
    float4 bb = *(const float4*)(bta + tid * 4);
    float4 o;
    o.x = (v.x - mu) * rs * gv.x + bb.x;
    o.y = (v.y - mu) * rs * gv.y + bb.y;
    o.z = (v.z - mu) * rs * gv.z + bb.z;
    o.w = (v.w - mu) * rs * gv.w + bb.w;
    *(float4*)(y + (size_t)row * 1024 + tid * 4) = o;
}

// ---------------------------------------------------------------------------
extern "C" void kernel_launch(void* const* d_in, const int* in_sizes, int n_in,
                              void* d_out, int out_size)
{
    const float* query    = (const float*)d_in[0];
    const float* key      = (const float*)d_in[1];
    const float* value    = (const float*)d_in[2];
    const int*   mask     = (const int*)  d_in[3];
    const float* relation = (const float*)d_in[4];
    const float* Wq       = (const float*)d_in[5];
    const float* Wk       = (const float*)d_in[6];
    const float* Wv       = (const float*)d_in[7];
    const float* fc_w     = (const float*)d_in[8];
    const float* fc_b     = (const float*)d_in[9];
    const float* ln_g     = (const float*)d_in[10];
    const float* ln_b     = (const float*)d_in[11];

    float* y = (float*)d_out;
    float* p = y + (size_t)YSIZE;

    static bool attr_set = false;
    if (!attr_set) {
        cudaFuncSetAttribute(mma_gemm,   cudaFuncAttributeMaxDynamicSharedMemorySize, SM_G);
        cudaFuncSetAttribute(scores_mma, cudaFuncAttributeMaxDynamicSharedMemorySize, SM_S);
        cudaFuncSetAttribute(att_mma,    cudaFuncAttributeMaxDynamicSharedMemorySize, SM_A);
        attr_set = true;
    }

    transpose_w<<<dim3(32, 32, 4), dim3(32, 8)>>>(Wq, Wk, Wv, fc_w);

    // QKV projections: one merged launch
    mma_gemm<<<dim3(8, 32, 3), 256, SM_G>>>(query, key, value, -1, nullptr, nullptr);

    scores_mma<<<dim3(8, 8, 64), 256, SM_S>>>(relation, mask);
    att_mma<<<dim3(8, 64), 256, SM_A>>>(p);

    mma_gemm<<<dim3(8, 32, 1), 256, SM_G>>>(nullptr, nullptr, nullptr, 3, fc_b, query);
    ln_kernel<<<Mc, 256>>>(ln_g, ln_b, y);
}